// round 7
// baseline (speedup 1.0000x reference)
#include <cuda_runtime.h>
#include <math.h>
#include <float.h>

#define BB 256
#define TT 200
#define EE 100
#define EP 112
#define HH 512
#define G4 2048
#define NCLS 5
#define VV 50000
#define MROWS (TT*BB)

// ---------------- static device scratch ----------------
__device__ float g_xe[(size_t)MROWS * EP];
__device__ float g_W0p[(size_t)G4 * EP];
__device__ float g_G[(size_t)MROWS * G4];
__device__ float g_h0s[(size_t)MROWS * HH];   // layer0 h archive (A for G1 GEMM)
__device__ float g_h1[4 * BB * HH];           // layer1 h ring buffer (4-deep)
__device__ float g_pooled[BB * HH];
__device__ int   g_last[BB];
__device__ unsigned g_bar[2][4];               // [layer][m-group] arrival counters

// ---------------- packed f32x2 helpers ----------------
__device__ __forceinline__ unsigned long long pk2(float lo, float hi) {
    unsigned long long r;
    asm("mov.b64 %0, {%1,%2};" : "=l"(r) : "f"(lo), "f"(hi));
    return r;
}
__device__ __forceinline__ void upk2(float& lo, float& hi, unsigned long long v) {
    asm("mov.b64 {%0,%1}, %2;" : "=f"(lo), "=f"(hi) : "l"(v));
}
__device__ __forceinline__ void fma2(unsigned long long& d, unsigned long long a, unsigned long long b) {
    asm("fma.rn.f32x2 %0, %1, %2, %0;" : "+l"(d) : "l"(a), "l"(b));
}
__device__ __forceinline__ void bar_arrive_release(unsigned* p) {
    unsigned dummy;
    asm volatile("atom.release.gpu.global.add.u32 %0, [%1], 1;"
                 : "=r"(dummy) : "l"(p) : "memory");
}
__device__ __forceinline__ unsigned bar_ld_acquire(const unsigned* p) {
    unsigned v;
    asm volatile("ld.acquire.gpu.global.u32 %0, [%1];" : "=r"(v) : "l"(p) : "memory");
    return v;
}
__device__ __forceinline__ float sigf(float x)   { return 1.0f / (1.0f + __expf(-x)); }
__device__ __forceinline__ float tanhf_(float x) { return 2.0f / (1.0f + __expf(-2.0f * x)) - 1.0f; }

// ---------------- prep kernels ----------------
__global__ void k_last(const int* __restrict__ X) {
    int b = threadIdx.x;
    if (b < BB) {
        int l = -1;
        for (int t = 0; t < TT; t++)
            if (X[b * TT + t] != VV) l = t;
        g_last[b] = l;
    }
}

__global__ void k_padw0(const float* __restrict__ W) {
    int idx = blockIdx.x * blockDim.x + threadIdx.x;
    if (idx < 8) ((unsigned*)g_bar)[idx] = 0u;      // reset barrier counters every call
    if (idx < G4 * EP) {
        int n = idx / EP, k = idx % EP;
        g_W0p[idx] = (k < EE) ? W[n * EE + k] : 0.0f;
    }
}

__global__ void k_gather(const int* __restrict__ X, const float* __restrict__ emb) {
    int row = blockIdx.x;
    int t = row / BB, b = row % BB;
    int tok = X[b * TT + t];
    const float* src = emb + (size_t)tok * EE;
    for (int e = threadIdx.x; e < EP; e += blockDim.x)
        g_xe[(size_t)row * EP + e] = (e < EE) ? src[e] : 0.0f;
}

// ---------------- input GEMM: C[M,4H] = A[M,K] @ W[4H,K]^T + bias ----------------
__global__ void __launch_bounds__(256) k_gemm(const float* __restrict__ Wihp,
                                              const float* __restrict__ bias,
                                              int which) {
    const float* A; const float* W; int K;
    if (which == 0) { A = g_xe;  W = g_W0p; K = EP; }
    else            { A = g_h0s; W = Wihp;  K = HH; }
    float* C = g_G;

    __shared__ float As[16][132];
    __shared__ float Bs[16][132];

    int m0 = blockIdx.y * 128, n0 = blockIdx.x * 128;
    int tx = threadIdx.x;
    int tn = tx & 15, tm = tx >> 4;

    unsigned long long acc[8][4];
#pragma unroll
    for (int i = 0; i < 8; i++)
#pragma unroll
        for (int j = 0; j < 4; j++) acc[i][j] = 0ull;

    int nt = K / 16;
    float4 va[2], vb[2];
#pragma unroll
    for (int i = 0; i < 2; i++) {
        int id = i * 256 + tx;
        int row = id >> 2, kq = (id & 3) * 4;
        va[i] = *(const float4*)(A + (size_t)(m0 + row) * K + kq);
        vb[i] = *(const float4*)(W + (size_t)(n0 + row) * K + kq);
    }

#pragma unroll 1
    for (int kt = 0; kt < nt; kt++) {
        float4 nva[2], nvb[2];
        if (kt + 1 < nt) {
            int k0n = (kt + 1) * 16;
#pragma unroll
            for (int i = 0; i < 2; i++) {
                int id = i * 256 + tx;
                int row = id >> 2, kq = (id & 3) * 4;
                nva[i] = *(const float4*)(A + (size_t)(m0 + row) * K + k0n + kq);
                nvb[i] = *(const float4*)(W + (size_t)(n0 + row) * K + k0n + kq);
            }
        }
#pragma unroll
        for (int i = 0; i < 2; i++) {
            int id = i * 256 + tx;
            int row = id >> 2, kq = (id & 3) * 4;
            As[kq + 0][row] = va[i].x; As[kq + 1][row] = va[i].y;
            As[kq + 2][row] = va[i].z; As[kq + 3][row] = va[i].w;
            Bs[kq + 0][row] = vb[i].x; Bs[kq + 1][row] = vb[i].y;
            Bs[kq + 2][row] = vb[i].z; Bs[kq + 3][row] = vb[i].w;
        }
        __syncthreads();
#pragma unroll
        for (int k = 0; k < 16; k++) {
            float4 a0 = *(const float4*)&As[k][tm * 4];
            float4 a1 = *(const float4*)&As[k][64 + tm * 4];
            unsigned long long pb[4];
            pb[0] = *(const unsigned long long*)&Bs[k][tn * 4];
            pb[1] = *(const unsigned long long*)&Bs[k][tn * 4 + 2];
            pb[2] = *(const unsigned long long*)&Bs[k][64 + tn * 4];
            pb[3] = *(const unsigned long long*)&Bs[k][64 + tn * 4 + 2];
            float am[8] = { a0.x, a0.y, a0.z, a0.w, a1.x, a1.y, a1.z, a1.w };
#pragma unroll
            for (int mi = 0; mi < 8; mi++) {
                unsigned long long pa = pk2(am[mi], am[mi]);
#pragma unroll
                for (int np = 0; np < 4; np++) fma2(acc[mi][np], pa, pb[np]);
            }
        }
        __syncthreads();
#pragma unroll
        for (int i = 0; i < 2; i++) { va[i] = nva[i]; vb[i] = nvb[i]; }
    }

    float4 bi0 = *(const float4*)(bias + n0 + tn * 4);
    float4 bi1 = *(const float4*)(bias + n0 + 64 + tn * 4);
#pragma unroll
    for (int mi = 0; mi < 8; mi++) {
        int row = m0 + ((mi < 4) ? (tm * 4 + mi) : (64 + tm * 4 + mi - 4));
        float4 o;
        upk2(o.x, o.y, acc[mi][0]); upk2(o.z, o.w, acc[mi][1]);
        o.x += bi0.x; o.y += bi0.y; o.z += bi0.z; o.w += bi0.w;
        *(float4*)(C + (size_t)row * G4 + n0 + tn * 4) = o;
        upk2(o.x, o.y, acc[mi][2]); upk2(o.z, o.w, acc[mi][3]);
        o.x += bi1.x; o.y += bi1.y; o.z += bi1.z; o.w += bi1.w;
        *(float4*)(C + (size_t)row * G4 + n0 + 64 + tn * 4) = o;
    }
}

// ---------------- persistent recurrence kernel ----------------
// grid (32 j-tiles, 4 m-tiles) = 128 CTAs, NOW 512 threads (4 warps/SMSP).
// CTA tile: 64m x (4g x 16j) x 512k.  Thread tile: 1m x 2j x 4g.
// Same k-accumulation order as R3/R6 -> bit-identical numerics.
#define WS_STRIDE 68
#define RS_WS   (HH * WS_STRIDE)                // 34816 floats
#define RS_AS   (2 * 32 * 130)                  // double-buffered dup-A staging
#define RS_SMEM ((RS_WS + RS_AS) * 4)
#define RTHREADS 512

template<int LAYER>
__global__ void __launch_bounds__(RTHREADS) k_recur(const float* __restrict__ Whh) {
    extern __shared__ float sm[];
    float* Ws  = sm;                 // [512][68]
    float* As2 = sm + RS_WS;         // [2][32][130]

    int j0 = blockIdx.x * 16;
    int m0 = blockIdx.y * 64;
    unsigned* bar = &g_bar[LAYER][blockIdx.y];
    int tx = threadIdx.x;
    int tj = tx & 7;                 // j-pair index 0..7
    int tm = tx >> 3;                // m-row 0..63

    // ---- stage W slab once ----
    // col c (0..63): blk=c>>5, tjj=(c>>2)&7, rem=c&3, g=2*blk+(rem>>1), j=j0+2*tjj+(rem&1)
    {
        int c = tx >> 3;                  // 8 threads per column
        int blk = c >> 5, tjj = (c >> 2) & 7, rem = c & 3;
        int g = 2 * blk + (rem >> 1);
        int jj = j0 + 2 * tjj + (rem & 1);
        int kb = (tx & 7) * 64;
        const float* wr = Whh + (size_t)(g * HH + jj) * HH + kb;
#pragma unroll 4
        for (int k = 0; k < 64; k += 4) {
            float4 v = *(const float4*)(wr + k);
            int kk = kb + k;
            Ws[(kk + 0) * WS_STRIDE + c] = v.x;
            Ws[(kk + 1) * WS_STRIDE + c] = v.y;
            Ws[(kk + 2) * WS_STRIDE + c] = v.z;
            Ws[(kk + 3) * WS_STRIDE + c] = v.w;
        }
    }
    __syncthreads();

    float2 cst = {0.f, 0.f};
    float2 pool;
    int lastv = 0;
    if (LAYER == 1) {
        pool = make_float2(-FLT_MAX, -FLT_MAX);
        lastv = g_last[m0 + tm];
    }

    // staging ids: each thread stages one float4 per kt: row = tm (0..63), q = (tx&7)*4
    int srow = tm, sq = (tx & 7) * 4;

    // prefetch gate inputs for t=0
    float2 gv[4];
    {
        const float* gr = g_G + (size_t)(m0 + tm) * G4 + j0 + 2 * tj;
#pragma unroll
        for (int g = 0; g < 4; g++) gv[g] = __ldcg((const float2*)(gr + g * 512));
    }

    for (int t = 0; t < TT; t++) {
        unsigned long long acc[4] = {0ull, 0ull, 0ull, 0ull};

        if (t > 0) {
            const float* hp = (LAYER == 0)
                ? g_h0s + (size_t)(t - 1) * BB * HH
                : g_h1 + (size_t)((t - 1) & 3) * BB * HH;
            float4 pA = __ldcg((const float4*)(hp + (size_t)(m0 + srow) * HH + sq));
#pragma unroll 1
            for (int kt = 0; kt < 16; kt++) {
                float4 nA;
                if (kt + 1 < 16) {
                    int k0n = (kt + 1) * 32;
                    nA = __ldcg((const float4*)(hp + (size_t)(m0 + srow) * HH + k0n + sq));
                }
                float* Ab = As2 + (kt & 1) * (32 * 130);
                *(unsigned long long*)&Ab[(sq + 0) * 130 + 2 * srow] = pk2(pA.x, pA.x);
                *(unsigned long long*)&Ab[(sq + 1) * 130 + 2 * srow] = pk2(pA.y, pA.y);
                *(unsigned long long*)&Ab[(sq + 2) * 130 + 2 * srow] = pk2(pA.z, pA.z);
                *(unsigned long long*)&Ab[(sq + 3) * 130 + 2 * srow] = pk2(pA.w, pA.w);
                __syncthreads();
                const float* WsK = Ws + (size_t)kt * 32 * WS_STRIDE;
#pragma unroll
                for (int k = 0; k < 32; k++) {
                    unsigned long long a0 = *(const unsigned long long*)&Ab[k * 130 + 2 * tm];
                    ulonglong2 b01 = *(const ulonglong2*)&WsK[k * WS_STRIDE + tj * 4];
                    ulonglong2 b23 = *(const ulonglong2*)&WsK[k * WS_STRIDE + 32 + tj * 4];
                    fma2(acc[0], a0, b01.x); fma2(acc[1], a0, b01.y);
                    fma2(acc[2], a0, b23.x); fma2(acc[3], a0, b23.y);
                }
                pA = nA;
            }
        }

        // ---- epilogue ----
        float* hout = (LAYER == 0)
            ? g_h0s + (size_t)t * BB * HH
            : g_h1 + (size_t)(t & 3) * BB * HH;
        {
            float i0, i1, f0, f1, gg0, gg1, o0, o1;
            upk2(i0, i1, acc[0]);
            upk2(f0, f1, acc[1]);
            upk2(gg0, gg1, acc[2]);
            upk2(o0, o1, acc[3]);
            i0 += gv[0].x; i1 += gv[0].y;
            f0 += gv[1].x; f1 += gv[1].y;
            gg0 += gv[2].x; gg1 += gv[2].y;
            o0 += gv[3].x; o1 += gv[3].y;

            float c0 = sigf(f0) * cst.x + sigf(i0) * tanhf_(gg0);
            float c1 = sigf(f1) * cst.y + sigf(i1) * tanhf_(gg1);
            cst.x = c0; cst.y = c1;
            float h0v = sigf(o0) * tanhf_(c0);
            float h1v = sigf(o1) * tanhf_(c1);

            int m = m0 + tm;
            __stcg((float2*)(hout + (size_t)m * HH + j0 + 2 * tj), make_float2(h0v, h1v));

            if (LAYER == 1 && t <= lastv) {
                pool.x = fmaxf(pool.x, h0v);
                pool.y = fmaxf(pool.y, h1v);
            }
        }

        // ---- inter-step barrier: per-m-group, release-arrive + acquire-poll ----
        if (t != TT - 1) {
            __threadfence();                    // release: order this thread's stores
            __syncthreads();
            if (tx == 0) bar_arrive_release(bar);
            // overlap: prefetch next step's gates while barrier settles
            {
                const float* gr = g_G + (size_t)(t + 1) * BB * G4
                                + (size_t)(m0 + tm) * G4 + j0 + 2 * tj;
#pragma unroll
                for (int g = 0; g < 4; g++) gv[g] = __ldcg((const float2*)(gr + g * 512));
            }
            if (tx == 0) {
                unsigned target = 32u * (unsigned)(t + 1);
                while (bar_ld_acquire(bar) < target) { }
            }
            __syncthreads();
            __threadfence();                    // acquire for all reader threads
        }
    }

    if (LAYER == 1) {
        int m = m0 + tm;
        *(float2*)&g_pooled[m * HH + j0 + 2 * tj] = pool;
    }
}

// ---------------- final projection ----------------
__global__ void k_logits(const float* __restrict__ Wout, const float* __restrict__ bout,
                         float* __restrict__ out) {
    int b = blockIdx.x;
    int tx = threadIdx.x;
    float p[NCLS] = {0, 0, 0, 0, 0};
    for (int k = tx; k < HH; k += 128) {
        float v = g_pooled[b * HH + k];
#pragma unroll
        for (int c = 0; c < NCLS; c++) p[c] += v * Wout[c * HH + k];
    }
#pragma unroll
    for (int off = 16; off; off >>= 1)
#pragma unroll
        for (int c = 0; c < NCLS; c++) p[c] += __shfl_down_sync(0xffffffffu, p[c], off);
    __shared__ float red[4][NCLS];
    if ((tx & 31) == 0)
#pragma unroll
        for (int c = 0; c < NCLS; c++) red[tx >> 5][c] = p[c];
    __syncthreads();
    if (tx == 0) {
#pragma unroll
        for (int c = 0; c < NCLS; c++)
            out[b * NCLS + c] = red[0][c] + red[1][c] + red[2][c] + red[3][c] + bout[c];
    }
}

// ---------------- launch ----------------
extern "C" void kernel_launch(void* const* d_in, const int* in_sizes, int n_in,
                              void* d_out, int out_size) {
    (void)in_sizes; (void)n_in; (void)out_size;
    const int*   X      = (const int*)d_in[0];
    const float* emb    = (const float*)d_in[1];
    const float* W_ih0  = (const float*)d_in[2];
    const float* W_hh0  = (const float*)d_in[3];
    const float* b0     = (const float*)d_in[4];
    const float* W_ih1  = (const float*)d_in[5];
    const float* W_hh1  = (const float*)d_in[6];
    const float* b1     = (const float*)d_in[7];
    const float* W_out  = (const float*)d_in[8];
    const float* b_out  = (const float*)d_in[9];
    float* out = (float*)d_out;

    cudaFuncSetAttribute(k_recur<0>, cudaFuncAttributeMaxDynamicSharedMemorySize, RS_SMEM);
    cudaFuncSetAttribute(k_recur<1>, cudaFuncAttributeMaxDynamicSharedMemorySize, RS_SMEM);

    // order keeps k_recur<0> in the ncu capture slot
    k_padw0<<<(G4 * EP + 255) / 256, 256>>>(W_ih0);              // 1 (also zeroes barriers)
    k_gather<<<MROWS, 128>>>(X, emb);                            // 2
    k_gemm<<<dim3(16, 400), 256>>>(nullptr, b0, 0);              // 3
    k_recur<0><<<dim3(32, 4), RTHREADS, RS_SMEM>>>(W_hh0);       // 4  <- capture target
    k_last<<<1, 256>>>(X);                                       // 5
    k_gemm<<<dim3(16, 400), 256>>>(W_ih1, b1, 1);                // 6
    k_recur<1><<<dim3(32, 4), RTHREADS, RS_SMEM>>>(W_hh1);       // 7
    k_logits<<<BB, 128>>>(W_out, b_out, out);                    // 8
}

// round 8
// speedup vs baseline: 1.4850x; 1.4850x over previous
#include <cuda_runtime.h>
#include <math.h>
#include <float.h>

#define BB 256
#define TT 200
#define EE 100
#define EP 112
#define HH 512
#define G4 2048
#define NCLS 5
#define VV 50000
#define MROWS (TT*BB)

// ---------------- static device scratch ----------------
__device__ float g_xe[(size_t)MROWS * EP];
__device__ float g_W0p[(size_t)G4 * EP];
__device__ float g_G[(size_t)MROWS * G4];
__device__ float g_h0s[(size_t)MROWS * HH];   // layer0 h archive (A for G1 GEMM)
__device__ float g_h1[4 * BB * HH];           // layer1 h ring buffer (4-deep)
__device__ float g_pooled[BB * HH];
__device__ int   g_last[BB];
__device__ unsigned g_bar[2][4];               // [layer][m-group] arrival counters

// ---------------- packed f32x2 helpers ----------------
__device__ __forceinline__ unsigned long long pk2(float lo, float hi) {
    unsigned long long r;
    asm("mov.b64 %0, {%1,%2};" : "=l"(r) : "f"(lo), "f"(hi));
    return r;
}
__device__ __forceinline__ void upk2(float& lo, float& hi, unsigned long long v) {
    asm("mov.b64 {%0,%1}, %2;" : "=f"(lo), "=f"(hi) : "l"(v));
}
__device__ __forceinline__ void fma2(unsigned long long& d, unsigned long long a, unsigned long long b) {
    asm("fma.rn.f32x2 %0, %1, %2, %0;" : "+l"(d) : "l"(a), "l"(b));
}
__device__ __forceinline__ void add2(unsigned long long& d, unsigned long long v) {
    asm("add.rn.f32x2 %0, %0, %1;" : "+l"(d) : "l"(v));
}
__device__ __forceinline__ void bar_arrive_release(unsigned* p) {
    unsigned dummy;
    asm volatile("atom.release.gpu.global.add.u32 %0, [%1], 1;"
                 : "=r"(dummy) : "l"(p) : "memory");
}
__device__ __forceinline__ unsigned bar_ld_acquire(const unsigned* p) {
    unsigned v;
    asm volatile("ld.acquire.gpu.global.u32 %0, [%1];" : "=r"(v) : "l"(p) : "memory");
    return v;
}
__device__ __forceinline__ void named_bar(int id) {
    asm volatile("bar.sync %0, 256;" :: "r"(id) : "memory");
}
__device__ __forceinline__ float sigf(float x)   { return 1.0f / (1.0f + __expf(-x)); }
__device__ __forceinline__ float tanhf_(float x) { return 2.0f / (1.0f + __expf(-2.0f * x)) - 1.0f; }

// ---------------- prep kernels ----------------
__global__ void k_last(const int* __restrict__ X) {
    int b = threadIdx.x;
    if (b < BB) {
        int l = -1;
        for (int t = 0; t < TT; t++)
            if (X[b * TT + t] != VV) l = t;
        g_last[b] = l;
    }
}

__global__ void k_padw0(const float* __restrict__ W) {
    int idx = blockIdx.x * blockDim.x + threadIdx.x;
    if (idx < 8) ((unsigned*)g_bar)[idx] = 0u;      // reset barrier counters every call
    if (idx < G4 * EP) {
        int n = idx / EP, k = idx % EP;
        g_W0p[idx] = (k < EE) ? W[n * EE + k] : 0.0f;
    }
}

__global__ void k_gather(const int* __restrict__ X, const float* __restrict__ emb) {
    int row = blockIdx.x;
    int t = row / BB, b = row % BB;
    int tok = X[b * TT + t];
    const float* src = emb + (size_t)tok * EE;
    for (int e = threadIdx.x; e < EP; e += blockDim.x)
        g_xe[(size_t)row * EP + e] = (e < EE) ? src[e] : 0.0f;
}

// ---------------- input GEMM: C[M,4H] = A[M,K] @ W[4H,K]^T + bias ----------------
__global__ void __launch_bounds__(256) k_gemm(const float* __restrict__ Wihp,
                                              const float* __restrict__ bias,
                                              int which) {
    const float* A; const float* W; int K;
    if (which == 0) { A = g_xe;  W = g_W0p; K = EP; }
    else            { A = g_h0s; W = Wihp;  K = HH; }
    float* C = g_G;

    __shared__ float As[16][132];
    __shared__ float Bs[16][132];

    int m0 = blockIdx.y * 128, n0 = blockIdx.x * 128;
    int tx = threadIdx.x;
    int tn = tx & 15, tm = tx >> 4;

    unsigned long long acc[8][4];
#pragma unroll
    for (int i = 0; i < 8; i++)
#pragma unroll
        for (int j = 0; j < 4; j++) acc[i][j] = 0ull;

    int nt = K / 16;
    float4 va[2], vb[2];
#pragma unroll
    for (int i = 0; i < 2; i++) {
        int id = i * 256 + tx;
        int row = id >> 2, kq = (id & 3) * 4;
        va[i] = *(const float4*)(A + (size_t)(m0 + row) * K + kq);
        vb[i] = *(const float4*)(W + (size_t)(n0 + row) * K + kq);
    }

#pragma unroll 1
    for (int kt = 0; kt < nt; kt++) {
        float4 nva[2], nvb[2];
        if (kt + 1 < nt) {
            int k0n = (kt + 1) * 16;
#pragma unroll
            for (int i = 0; i < 2; i++) {
                int id = i * 256 + tx;
                int row = id >> 2, kq = (id & 3) * 4;
                nva[i] = *(const float4*)(A + (size_t)(m0 + row) * K + k0n + kq);
                nvb[i] = *(const float4*)(W + (size_t)(n0 + row) * K + k0n + kq);
            }
        }
#pragma unroll
        for (int i = 0; i < 2; i++) {
            int id = i * 256 + tx;
            int row = id >> 2, kq = (id & 3) * 4;
            As[kq + 0][row] = va[i].x; As[kq + 1][row] = va[i].y;
            As[kq + 2][row] = va[i].z; As[kq + 3][row] = va[i].w;
            Bs[kq + 0][row] = vb[i].x; Bs[kq + 1][row] = vb[i].y;
            Bs[kq + 2][row] = vb[i].z; Bs[kq + 3][row] = vb[i].w;
        }
        __syncthreads();
#pragma unroll
        for (int k = 0; k < 16; k++) {
            float4 a0 = *(const float4*)&As[k][tm * 4];
            float4 a1 = *(const float4*)&As[k][64 + tm * 4];
            unsigned long long pb[4];
            pb[0] = *(const unsigned long long*)&Bs[k][tn * 4];
            pb[1] = *(const unsigned long long*)&Bs[k][tn * 4 + 2];
            pb[2] = *(const unsigned long long*)&Bs[k][64 + tn * 4];
            pb[3] = *(const unsigned long long*)&Bs[k][64 + tn * 4 + 2];
            float am[8] = { a0.x, a0.y, a0.z, a0.w, a1.x, a1.y, a1.z, a1.w };
#pragma unroll
            for (int mi = 0; mi < 8; mi++) {
                unsigned long long pa = pk2(am[mi], am[mi]);
#pragma unroll
                for (int np = 0; np < 4; np++) fma2(acc[mi][np], pa, pb[np]);
            }
        }
        __syncthreads();
#pragma unroll
        for (int i = 0; i < 2; i++) { va[i] = nva[i]; vb[i] = nvb[i]; }
    }

    float4 bi0 = *(const float4*)(bias + n0 + tn * 4);
    float4 bi1 = *(const float4*)(bias + n0 + 64 + tn * 4);
#pragma unroll
    for (int mi = 0; mi < 8; mi++) {
        int row = m0 + ((mi < 4) ? (tm * 4 + mi) : (64 + tm * 4 + mi - 4));
        float4 o;
        upk2(o.x, o.y, acc[mi][0]); upk2(o.z, o.w, acc[mi][1]);
        o.x += bi0.x; o.y += bi0.y; o.z += bi0.z; o.w += bi0.w;
        *(float4*)(C + (size_t)row * G4 + n0 + tn * 4) = o;
        upk2(o.x, o.y, acc[mi][2]); upk2(o.z, o.w, acc[mi][3]);
        o.x += bi1.x; o.y += bi1.y; o.z += bi1.z; o.w += bi1.w;
        *(float4*)(C + (size_t)row * G4 + n0 + 64 + tn * 4) = o;
    }
}

// ---------------- persistent recurrence kernel ----------------
// grid (32 j-tiles, 4 m-tiles) = 128 CTAs, 512 threads, warp-level k-split:
//   low 256 threads:  k in [0,256)   (kt 0..7),  buffers 0/1, named bar 1
//   high 256 threads: k in [256,512) (kt 8..15), buffers 2/3, named bar 2
// Each half = exact R6 pipeline (thread tile 2m x 2j x 4g).
// End of step: high stores partial accs to smem; low merges + epilogue.
#define WS_STRIDE 68
#define RS_WS   (HH * WS_STRIDE)                // 34816 floats
#define RS_BUF  (32 * 130)                      // one staging buffer
#define RS_PART (4 * RS_BUF)                    // partials offset within As2
#define RS_AS   (4 * RS_BUF + 4096)             // 4 buffers + 256*8 ull partials
#define RS_SMEM ((RS_WS + RS_AS) * 4)
#define RTHREADS 512

template<int LAYER>
__global__ void __launch_bounds__(RTHREADS) k_recur(const float* __restrict__ Whh) {
    extern __shared__ float sm[];
    float* Ws  = sm;                 // [512][68]
    float* As2 = sm + RS_WS;         // [4][32][130] + partials

    int j0 = blockIdx.x * 16;
    int m0 = blockIdx.y * 64;
    unsigned* bar = &g_bar[LAYER][blockIdx.y];
    int tx = threadIdx.x;
    int half = tx >> 8;              // 0: k 0..255, 1: k 256..511
    int txh = tx & 255;
    int tj = txh & 7, tm = txh >> 3; // tj 0..7, tm 0..31
    int barid = 1 + half;
    int ktbase = half * 8;
    float* AbBase = As2 + half * 2 * RS_BUF;

    // ---- stage W slab once (512 threads, proven R7 pattern) ----
    {
        int c = tx >> 3;                  // 0..63
        int blk = c >> 5, tjj = (c >> 2) & 7, rem = c & 3;
        int g = 2 * blk + (rem >> 1);
        int jj = j0 + 2 * tjj + (rem & 1);
        int kb = (tx & 7) * 64;
        const float* wr = Whh + (size_t)(g * HH + jj) * HH + kb;
#pragma unroll 4
        for (int k = 0; k < 64; k += 4) {
            float4 v = *(const float4*)(wr + k);
            int kk = kb + k;
            Ws[(kk + 0) * WS_STRIDE + c] = v.x;
            Ws[(kk + 1) * WS_STRIDE + c] = v.y;
            Ws[(kk + 2) * WS_STRIDE + c] = v.z;
            Ws[(kk + 3) * WS_STRIDE + c] = v.w;
        }
    }
    __syncthreads();

    float2 cst[2] = { {0.f, 0.f}, {0.f, 0.f} };
    float2 pool[2];
    int lastv[2] = {0, 0};
    if (LAYER == 1 && half == 0) {
        pool[0] = make_float2(-FLT_MAX, -FLT_MAX);
        pool[1] = make_float2(-FLT_MAX, -FLT_MAX);
        lastv[0] = g_last[m0 + 2 * tm];
        lastv[1] = g_last[m0 + 2 * tm + 1];
    }

    // staging ids (R6 proven mapping, per-half)
    int sr0 = txh >> 3, sq0 = (txh & 7) * 4;
    int sr1 = 32 + (txh >> 3);

    // partial-accumulator exchange slot
    ulonglong2* pp = (ulonglong2*)(As2 + RS_PART) + (size_t)txh * 4;

    // prefetch gate inputs for t=0 (low half only)
    float2 gv[2][4];
    if (half == 0) {
#pragma unroll
        for (int mi = 0; mi < 2; mi++) {
            const float* gr = g_G + (size_t)(m0 + 2 * tm + mi) * G4 + j0 + 2 * tj;
#pragma unroll
            for (int g = 0; g < 4; g++) gv[mi][g] = __ldcg((const float2*)(gr + g * 512));
        }
    }

    for (int t = 0; t < TT; t++) {
        unsigned long long acc[2][4];
#pragma unroll
        for (int mi = 0; mi < 2; mi++)
#pragma unroll
            for (int g = 0; g < 4; g++) acc[mi][g] = 0ull;

        if (t > 0) {
            const float* hp = (LAYER == 0)
                ? g_h0s + (size_t)(t - 1) * BB * HH
                : g_h1 + (size_t)((t - 1) & 3) * BB * HH;
            int k00 = ktbase * 32;
            float4 pA = __ldcg((const float4*)(hp + (size_t)(m0 + sr0) * HH + k00 + sq0));
            float4 pB = __ldcg((const float4*)(hp + (size_t)(m0 + sr1) * HH + k00 + sq0));
#pragma unroll 1
            for (int kt2 = 0; kt2 < 8; kt2++) {
                int kt = ktbase + kt2;
                float4 nA, nB;
                if (kt2 + 1 < 8) {
                    int k0n = (kt + 1) * 32;
                    nA = __ldcg((const float4*)(hp + (size_t)(m0 + sr0) * HH + k0n + sq0));
                    nB = __ldcg((const float4*)(hp + (size_t)(m0 + sr1) * HH + k0n + sq0));
                }
                float* Ab = AbBase + (kt2 & 1) * RS_BUF;
                *(unsigned long long*)&Ab[(sq0 + 0) * 130 + 2 * sr0] = pk2(pA.x, pA.x);
                *(unsigned long long*)&Ab[(sq0 + 1) * 130 + 2 * sr0] = pk2(pA.y, pA.y);
                *(unsigned long long*)&Ab[(sq0 + 2) * 130 + 2 * sr0] = pk2(pA.z, pA.z);
                *(unsigned long long*)&Ab[(sq0 + 3) * 130 + 2 * sr0] = pk2(pA.w, pA.w);
                *(unsigned long long*)&Ab[(sq0 + 0) * 130 + 2 * sr1] = pk2(pB.x, pB.x);
                *(unsigned long long*)&Ab[(sq0 + 1) * 130 + 2 * sr1] = pk2(pB.y, pB.y);
                *(unsigned long long*)&Ab[(sq0 + 2) * 130 + 2 * sr1] = pk2(pB.z, pB.z);
                *(unsigned long long*)&Ab[(sq0 + 3) * 130 + 2 * sr1] = pk2(pB.w, pB.w);
                named_bar(barid);
                const float* WsK = Ws + (size_t)kt * 32 * WS_STRIDE;
#pragma unroll
                for (int k = 0; k < 32; k++) {
                    unsigned long long a0 = *(const unsigned long long*)&Ab[k * 130 + 4 * tm];
                    unsigned long long a1 = *(const unsigned long long*)&Ab[k * 130 + 4 * tm + 2];
                    ulonglong2 b01 = *(const ulonglong2*)&WsK[k * WS_STRIDE + tj * 4];
                    ulonglong2 b23 = *(const ulonglong2*)&WsK[k * WS_STRIDE + 32 + tj * 4];
                    fma2(acc[0][0], a0, b01.x); fma2(acc[0][1], a0, b01.y);
                    fma2(acc[0][2], a0, b23.x); fma2(acc[0][3], a0, b23.y);
                    fma2(acc[1][0], a1, b01.x); fma2(acc[1][1], a1, b01.y);
                    fma2(acc[1][2], a1, b23.x); fma2(acc[1][3], a1, b23.y);
                }
                pA = nA; pB = nB;
            }
        }

        // ---- merge halves: high stores partials, low adds ----
        if (half) {
            pp[0] = make_ulonglong2(acc[0][0], acc[0][1]);
            pp[1] = make_ulonglong2(acc[0][2], acc[0][3]);
            pp[2] = make_ulonglong2(acc[1][0], acc[1][1]);
            pp[3] = make_ulonglong2(acc[1][2], acc[1][3]);
        }
        __syncthreads();

        if (half == 0) {
            ulonglong2 q0 = pp[0], q1 = pp[1], q2 = pp[2], q3 = pp[3];
            add2(acc[0][0], q0.x); add2(acc[0][1], q0.y);
            add2(acc[0][2], q1.x); add2(acc[0][3], q1.y);
            add2(acc[1][0], q2.x); add2(acc[1][1], q2.y);
            add2(acc[1][2], q3.x); add2(acc[1][3], q3.y);

            // ---- epilogue (R6, unchanged) ----
            float* hout = (LAYER == 0)
                ? g_h0s + (size_t)t * BB * HH
                : g_h1 + (size_t)(t & 3) * BB * HH;
#pragma unroll
            for (int mi = 0; mi < 2; mi++) {
                float i0, i1, f0, f1, gg0, gg1, o0, o1;
                upk2(i0, i1, acc[mi][0]);
                upk2(f0, f1, acc[mi][1]);
                upk2(gg0, gg1, acc[mi][2]);
                upk2(o0, o1, acc[mi][3]);
                i0 += gv[mi][0].x; i1 += gv[mi][0].y;
                f0 += gv[mi][1].x; f1 += gv[mi][1].y;
                gg0 += gv[mi][2].x; gg1 += gv[mi][2].y;
                o0 += gv[mi][3].x; o1 += gv[mi][3].y;

                float c0 = sigf(f0) * cst[mi].x + sigf(i0) * tanhf_(gg0);
                float c1 = sigf(f1) * cst[mi].y + sigf(i1) * tanhf_(gg1);
                cst[mi].x = c0; cst[mi].y = c1;
                float h0v = sigf(o0) * tanhf_(c0);
                float h1v = sigf(o1) * tanhf_(c1);

                int m = m0 + 2 * tm + mi;
                __stcg((float2*)(hout + (size_t)m * HH + j0 + 2 * tj), make_float2(h0v, h1v));

                if (LAYER == 1 && t <= lastv[mi]) {
                    pool[mi].x = fmaxf(pool[mi].x, h0v);
                    pool[mi].y = fmaxf(pool[mi].y, h1v);
                }
            }
        }

        // ---- inter-step barrier: per-m-group, release-arrive + acquire-poll ----
        if (t != TT - 1) {
            __threadfence();                    // release: order h stores
            __syncthreads();
            if (tx == 0) bar_arrive_release(bar);
            if (half == 0) {
                // overlap: prefetch next step's gates while barrier settles
                const float* Gt = g_G + (size_t)(t + 1) * BB * G4;
#pragma unroll
                for (int mi = 0; mi < 2; mi++) {
                    const float* gr = Gt + (size_t)(m0 + 2 * tm + mi) * G4 + j0 + 2 * tj;
#pragma unroll
                    for (int g = 0; g < 4; g++) gv[mi][g] = __ldcg((const float2*)(gr + g * 512));
                }
            }
            if (tx == 0) {
                unsigned target = 32u * (unsigned)(t + 1);
                while (bar_ld_acquire(bar) < target) { }
            }
            __syncthreads();
            __threadfence();                    // acquire for all reader threads
        }
    }

    if (LAYER == 1 && half == 0) {
#pragma unroll
        for (int mi = 0; mi < 2; mi++) {
            int m = m0 + 2 * tm + mi;
            *(float2*)&g_pooled[m * HH + j0 + 2 * tj] = pool[mi];
        }
    }
}

// ---------------- final projection ----------------
__global__ void k_logits(const float* __restrict__ Wout, const float* __restrict__ bout,
                         float* __restrict__ out) {
    int b = blockIdx.x;
    int tx = threadIdx.x;
    float p[NCLS] = {0, 0, 0, 0, 0};
    for (int k = tx; k < HH; k += 128) {
        float v = g_pooled[b * HH + k];
#pragma unroll
        for (int c = 0; c < NCLS; c++) p[c] += v * Wout[c * HH + k];
    }
#pragma unroll
    for (int off = 16; off; off >>= 1)
#pragma unroll
        for (int c = 0; c < NCLS; c++) p[c] += __shfl_down_sync(0xffffffffu, p[c], off);
    __shared__ float red[4][NCLS];
    if ((tx & 31) == 0)
#pragma unroll
        for (int c = 0; c < NCLS; c++) red[tx >> 5][c] = p[c];
    __syncthreads();
    if (tx == 0) {
#pragma unroll
        for (int c = 0; c < NCLS; c++)
            out[b * NCLS + c] = red[0][c] + red[1][c] + red[2][c] + red[3][c] + bout[c];
    }
}

// ---------------- launch ----------------
extern "C" void kernel_launch(void* const* d_in, const int* in_sizes, int n_in,
                              void* d_out, int out_size) {
    (void)in_sizes; (void)n_in; (void)out_size;
    const int*   X      = (const int*)d_in[0];
    const float* emb    = (const float*)d_in[1];
    const float* W_ih0  = (const float*)d_in[2];
    const float* W_hh0  = (const float*)d_in[3];
    const float* b0     = (const float*)d_in[4];
    const float* W_ih1  = (const float*)d_in[5];
    const float* W_hh1  = (const float*)d_in[6];
    const float* b1     = (const float*)d_in[7];
    const float* W_out  = (const float*)d_in[8];
    const float* b_out  = (const float*)d_in[9];
    float* out = (float*)d_out;

    cudaFuncSetAttribute(k_recur<0>, cudaFuncAttributeMaxDynamicSharedMemorySize, RS_SMEM);
    cudaFuncSetAttribute(k_recur<1>, cudaFuncAttributeMaxDynamicSharedMemorySize, RS_SMEM);

    // order keeps k_recur<0> in the ncu capture slot
    k_padw0<<<(G4 * EP + 255) / 256, 256>>>(W_ih0);              // 1 (also zeroes barriers)
    k_gather<<<MROWS, 128>>>(X, emb);                            // 2
    k_gemm<<<dim3(16, 400), 256>>>(nullptr, b0, 0);              // 3
    k_recur<0><<<dim3(32, 4), RTHREADS, RS_SMEM>>>(W_hh0);       // 4  <- capture target
    k_last<<<1, 256>>>(X);                                       // 5
    k_gemm<<<dim3(16, 400), 256>>>(W_ih1, b1, 1);                // 6
    k_recur<1><<<dim3(32, 4), RTHREADS, RS_SMEM>>>(W_hh1);       // 7
    k_logits<<<BB, 128>>>(W_out, b_out, out);                    // 8
}

// round 9
// speedup vs baseline: 1.5906x; 1.0711x over previous
#include <cuda_runtime.h>
#include <math.h>
#include <float.h>

#define BB 256
#define TT 200
#define EE 100
#define EP 112
#define HH 512
#define G4 2048
#define NCLS 5
#define VV 50000
#define MROWS (TT*BB)

// ---------------- static device scratch ----------------
__device__ float g_xe[(size_t)MROWS * EP];
__device__ float g_W0p[(size_t)G4 * EP];
__device__ float g_G[(size_t)MROWS * G4];
__device__ float g_h0s[(size_t)MROWS * HH];   // layer0 h archive (A for G1 GEMM)
__device__ float g_h1[4 * BB * HH];           // layer1 h ring buffer (4-deep)
__device__ float g_pooled[BB * HH];
__device__ int   g_last[BB];
__device__ unsigned g_bar[2][4];               // [layer][m-group] arrival counters

// ---------------- packed f32x2 helpers ----------------
__device__ __forceinline__ unsigned long long pk2(float lo, float hi) {
    unsigned long long r;
    asm("mov.b64 %0, {%1,%2};" : "=l"(r) : "f"(lo), "f"(hi));
    return r;
}
__device__ __forceinline__ void upk2(float& lo, float& hi, unsigned long long v) {
    asm("mov.b64 {%0,%1}, %2;" : "=f"(lo), "=f"(hi) : "l"(v));
}
__device__ __forceinline__ void fma2(unsigned long long& d, unsigned long long a, unsigned long long b) {
    asm("fma.rn.f32x2 %0, %1, %2, %0;" : "+l"(d) : "l"(a), "l"(b));
}
__device__ __forceinline__ void add2(unsigned long long& d, unsigned long long v) {
    asm("add.rn.f32x2 %0, %0, %1;" : "+l"(d) : "l"(v));
}
__device__ __forceinline__ void bar_arrive_release(unsigned* p) {
    unsigned dummy;
    asm volatile("atom.release.gpu.global.add.u32 %0, [%1], 1;"
                 : "=r"(dummy) : "l"(p) : "memory");
}
__device__ __forceinline__ unsigned bar_ld_acquire(const unsigned* p) {
    unsigned v;
    asm volatile("ld.acquire.gpu.global.u32 %0, [%1];" : "=r"(v) : "l"(p) : "memory");
    return v;
}
__device__ __forceinline__ void named_bar(int id) {
    asm volatile("bar.sync %0, 128;" :: "r"(id) : "memory");
}
__device__ __forceinline__ float sigf(float x)   { return 1.0f / (1.0f + __expf(-x)); }
__device__ __forceinline__ float tanhf_(float x) { return 2.0f / (1.0f + __expf(-2.0f * x)) - 1.0f; }

// ---------------- prep kernels ----------------
__global__ void k_last(const int* __restrict__ X) {
    int b = threadIdx.x;
    if (b < BB) {
        int l = -1;
        for (int t = 0; t < TT; t++)
            if (X[b * TT + t] != VV) l = t;
        g_last[b] = l;
    }
}

__global__ void k_padw0(const float* __restrict__ W) {
    int idx = blockIdx.x * blockDim.x + threadIdx.x;
    if (idx < 8) ((unsigned*)g_bar)[idx] = 0u;      // reset barrier counters every call
    if (idx < G4 * EP) {
        int n = idx / EP, k = idx % EP;
        g_W0p[idx] = (k < EE) ? W[n * EE + k] : 0.0f;
    }
}

__global__ void k_gather(const int* __restrict__ X, const float* __restrict__ emb) {
    int row = blockIdx.x;
    int t = row / BB, b = row % BB;
    int tok = X[b * TT + t];
    const float* src = emb + (size_t)tok * EE;
    for (int e = threadIdx.x; e < EP; e += blockDim.x)
        g_xe[(size_t)row * EP + e] = (e < EE) ? src[e] : 0.0f;
}

// ---------------- input GEMM: C[M,4H] = A[M,K] @ W[4H,K]^T + bias ----------------
__global__ void __launch_bounds__(256) k_gemm(const float* __restrict__ Wihp,
                                              const float* __restrict__ bias,
                                              int which) {
    const float* A; const float* W; int K;
    if (which == 0) { A = g_xe;  W = g_W0p; K = EP; }
    else            { A = g_h0s; W = Wihp;  K = HH; }
    float* C = g_G;

    __shared__ float As[16][132];
    __shared__ float Bs[16][132];

    int m0 = blockIdx.y * 128, n0 = blockIdx.x * 128;
    int tx = threadIdx.x;
    int tn = tx & 15, tm = tx >> 4;

    unsigned long long acc[8][4];
#pragma unroll
    for (int i = 0; i < 8; i++)
#pragma unroll
        for (int j = 0; j < 4; j++) acc[i][j] = 0ull;

    int nt = K / 16;
    float4 va[2], vb[2];
#pragma unroll
    for (int i = 0; i < 2; i++) {
        int id = i * 256 + tx;
        int row = id >> 2, kq = (id & 3) * 4;
        va[i] = *(const float4*)(A + (size_t)(m0 + row) * K + kq);
        vb[i] = *(const float4*)(W + (size_t)(n0 + row) * K + kq);
    }

#pragma unroll 1
    for (int kt = 0; kt < nt; kt++) {
        float4 nva[2], nvb[2];
        if (kt + 1 < nt) {
            int k0n = (kt + 1) * 16;
#pragma unroll
            for (int i = 0; i < 2; i++) {
                int id = i * 256 + tx;
                int row = id >> 2, kq = (id & 3) * 4;
                nva[i] = *(const float4*)(A + (size_t)(m0 + row) * K + k0n + kq);
                nvb[i] = *(const float4*)(W + (size_t)(n0 + row) * K + k0n + kq);
            }
        }
#pragma unroll
        for (int i = 0; i < 2; i++) {
            int id = i * 256 + tx;
            int row = id >> 2, kq = (id & 3) * 4;
            As[kq + 0][row] = va[i].x; As[kq + 1][row] = va[i].y;
            As[kq + 2][row] = va[i].z; As[kq + 3][row] = va[i].w;
            Bs[kq + 0][row] = vb[i].x; Bs[kq + 1][row] = vb[i].y;
            Bs[kq + 2][row] = vb[i].z; Bs[kq + 3][row] = vb[i].w;
        }
        __syncthreads();
#pragma unroll
        for (int k = 0; k < 16; k++) {
            float4 a0 = *(const float4*)&As[k][tm * 4];
            float4 a1 = *(const float4*)&As[k][64 + tm * 4];
            unsigned long long pb[4];
            pb[0] = *(const unsigned long long*)&Bs[k][tn * 4];
            pb[1] = *(const unsigned long long*)&Bs[k][tn * 4 + 2];
            pb[2] = *(const unsigned long long*)&Bs[k][64 + tn * 4];
            pb[3] = *(const unsigned long long*)&Bs[k][64 + tn * 4 + 2];
            float am[8] = { a0.x, a0.y, a0.z, a0.w, a1.x, a1.y, a1.z, a1.w };
#pragma unroll
            for (int mi = 0; mi < 8; mi++) {
                unsigned long long pa = pk2(am[mi], am[mi]);
#pragma unroll
                for (int np = 0; np < 4; np++) fma2(acc[mi][np], pa, pb[np]);
            }
        }
        __syncthreads();
#pragma unroll
        for (int i = 0; i < 2; i++) { va[i] = nva[i]; vb[i] = nvb[i]; }
    }

    float4 bi0 = *(const float4*)(bias + n0 + tn * 4);
    float4 bi1 = *(const float4*)(bias + n0 + 64 + tn * 4);
#pragma unroll
    for (int mi = 0; mi < 8; mi++) {
        int row = m0 + ((mi < 4) ? (tm * 4 + mi) : (64 + tm * 4 + mi - 4));
        float4 o;
        upk2(o.x, o.y, acc[mi][0]); upk2(o.z, o.w, acc[mi][1]);
        o.x += bi0.x; o.y += bi0.y; o.z += bi0.z; o.w += bi0.w;
        *(float4*)(C + (size_t)row * G4 + n0 + tn * 4) = o;
        upk2(o.x, o.y, acc[mi][2]); upk2(o.z, o.w, acc[mi][3]);
        o.x += bi1.x; o.y += bi1.y; o.z += bi1.z; o.w += bi1.w;
        *(float4*)(C + (size_t)row * G4 + n0 + 64 + tn * 4) = o;
    }
}

// ---------------- persistent recurrence kernel ----------------
// grid (32 j-tiles, 4 m-tiles) = 128 CTAs, 256 threads, k-split halves:
//   low 128 threads:  k in [0,256)   (kt 0..7),  buffers 0/1, named bar 1
//   high 128 threads: k in [256,512) (kt 8..15), buffers 2/3, named bar 2
// Thread tile: 4m x 2j x 4g  ->  per k: 4 LDS.128 feed 16 fma2 (ratio 4:1).
// End of step: high stores 16 partial accs; low merges + epilogue.
#define WS_STRIDE 68
#define RS_WS   (HH * WS_STRIDE)                // 34816 floats
#define AB_STRIDE 132
#define RS_BUF  (32 * AB_STRIDE)                // 4224 floats per staging buffer
#define RS_PART (4 * RS_BUF)                    // partials offset (floats)
#define RS_AS   (4 * RS_BUF + 4096)             // 4 buffers + 128 thr * 16 ull
#define RS_SMEM ((RS_WS + RS_AS) * 4)           // 223232 B
#define RTHREADS 256

template<int LAYER>
__global__ void __launch_bounds__(RTHREADS) k_recur(const float* __restrict__ Whh) {
    extern __shared__ float sm[];
    float* Ws  = sm;                 // [512][68]
    float* As2 = sm + RS_WS;         // [4][32][132] + partials

    int j0 = blockIdx.x * 16;
    int m0 = blockIdx.y * 64;
    unsigned* bar = &g_bar[LAYER][blockIdx.y];
    int tx = threadIdx.x;
    int half = tx >> 7;              // 0: k 0..255, 1: k 256..511
    int txh = tx & 127;
    int tj = txh & 7;                // j-pair 0..7
    int tmq = txh >> 3;              // m-quad 0..15 (4 m-rows each)
    int barid = 1 + half;
    int ktbase = half * 8;
    float* AbBase = As2 + half * 2 * RS_BUF;

    // ---- stage W slab once (256 threads, proven R6 pattern) ----
    {
        int c = tx >> 2;                  // 0..63
        int blk = c >> 5, tjj = (c >> 2) & 7, rem = c & 3;
        int g = 2 * blk + (rem >> 1);
        int jj = j0 + 2 * tjj + (rem & 1);
        int kb = (tx & 3) * 128;
        const float* wr = Whh + (size_t)(g * HH + jj) * HH + kb;
#pragma unroll 4
        for (int k = 0; k < 128; k += 4) {
            float4 v = *(const float4*)(wr + k);
            int kk = kb + k;
            Ws[(kk + 0) * WS_STRIDE + c] = v.x;
            Ws[(kk + 1) * WS_STRIDE + c] = v.y;
            Ws[(kk + 2) * WS_STRIDE + c] = v.z;
            Ws[(kk + 3) * WS_STRIDE + c] = v.w;
        }
    }
    __syncthreads();

    float2 cst[4] = { {0.f,0.f}, {0.f,0.f}, {0.f,0.f}, {0.f,0.f} };
    float2 pool[4];
    int lastv[4] = {0, 0, 0, 0};
    if (LAYER == 1 && half == 0) {
#pragma unroll
        for (int mi = 0; mi < 4; mi++) {
            pool[mi] = make_float2(-FLT_MAX, -FLT_MAX);
            lastv[mi] = g_last[m0 + 4 * tmq + mi];
        }
    }

    // staging ids: thread stages m-row srow, 16 k-values (qg selects k-half of chunk)
    int srow = txh & 63, qg = txh >> 6, sq = qg * 16;

    // partial-accumulator exchange slot (16 ull per high thread)
    ulonglong2* pp = (ulonglong2*)(As2 + RS_PART) + (size_t)txh * 8;

    // prefetch gate inputs for t=0 (low half only)
    float2 gv[4][4];
    if (half == 0) {
#pragma unroll
        for (int mi = 0; mi < 4; mi++) {
            const float* gr = g_G + (size_t)(m0 + 4 * tmq + mi) * G4 + j0 + 2 * tj;
#pragma unroll
            for (int g = 0; g < 4; g++) gv[mi][g] = __ldcg((const float2*)(gr + g * 512));
        }
    }

    for (int t = 0; t < TT; t++) {
        unsigned long long acc[4][4];
#pragma unroll
        for (int mi = 0; mi < 4; mi++)
#pragma unroll
            for (int g = 0; g < 4; g++) acc[mi][g] = 0ull;

        if (t > 0) {
            const float* hp = (LAYER == 0)
                ? g_h0s + (size_t)(t - 1) * BB * HH
                : g_h1 + (size_t)((t - 1) & 3) * BB * HH;
            const float* hrow = hp + (size_t)(m0 + srow) * HH;
            int k00 = ktbase * 32 + sq;
            float4 pv[4];
#pragma unroll
            for (int i = 0; i < 4; i++)
                pv[i] = __ldcg((const float4*)(hrow + k00 + 4 * i));
#pragma unroll 1
            for (int kt2 = 0; kt2 < 8; kt2++) {
                int kt = ktbase + kt2;
                float4 nv[4];
                if (kt2 + 1 < 8) {
                    int k0n = (kt + 1) * 32 + sq;
#pragma unroll
                    for (int i = 0; i < 4; i++)
                        nv[i] = __ldcg((const float4*)(hrow + k0n + 4 * i));
                }
                float* Ab = AbBase + (kt2 & 1) * RS_BUF;
#pragma unroll
                for (int i = 0; i < 4; i++) {
                    int kq = sq + 4 * i;
                    *(unsigned long long*)&Ab[(kq + 0) * AB_STRIDE + 2 * srow] = pk2(pv[i].x, pv[i].x);
                    *(unsigned long long*)&Ab[(kq + 1) * AB_STRIDE + 2 * srow] = pk2(pv[i].y, pv[i].y);
                    *(unsigned long long*)&Ab[(kq + 2) * AB_STRIDE + 2 * srow] = pk2(pv[i].z, pv[i].z);
                    *(unsigned long long*)&Ab[(kq + 3) * AB_STRIDE + 2 * srow] = pk2(pv[i].w, pv[i].w);
                }
                named_bar(barid);
                const float* WsK = Ws + (size_t)kt * 32 * WS_STRIDE;
#pragma unroll
                for (int k = 0; k < 32; k++) {
                    ulonglong2 a01 = *(const ulonglong2*)&Ab[k * AB_STRIDE + 8 * tmq];
                    ulonglong2 a23 = *(const ulonglong2*)&Ab[k * AB_STRIDE + 8 * tmq + 4];
                    ulonglong2 b01 = *(const ulonglong2*)&WsK[k * WS_STRIDE + tj * 4];
                    ulonglong2 b23 = *(const ulonglong2*)&WsK[k * WS_STRIDE + 32 + tj * 4];
                    fma2(acc[0][0], a01.x, b01.x); fma2(acc[0][1], a01.x, b01.y);
                    fma2(acc[0][2], a01.x, b23.x); fma2(acc[0][3], a01.x, b23.y);
                    fma2(acc[1][0], a01.y, b01.x); fma2(acc[1][1], a01.y, b01.y);
                    fma2(acc[1][2], a01.y, b23.x); fma2(acc[1][3], a01.y, b23.y);
                    fma2(acc[2][0], a23.x, b01.x); fma2(acc[2][1], a23.x, b01.y);
                    fma2(acc[2][2], a23.x, b23.x); fma2(acc[2][3], a23.x, b23.y);
                    fma2(acc[3][0], a23.y, b01.x); fma2(acc[3][1], a23.y, b01.y);
                    fma2(acc[3][2], a23.y, b23.x); fma2(acc[3][3], a23.y, b23.y);
                }
#pragma unroll
                for (int i = 0; i < 4; i++) pv[i] = nv[i];
            }
        }

        // ---- merge halves: high stores partials, low adds ----
        if (half) {
#pragma unroll
            for (int mi = 0; mi < 4; mi++) {
                pp[2 * mi]     = make_ulonglong2(acc[mi][0], acc[mi][1]);
                pp[2 * mi + 1] = make_ulonglong2(acc[mi][2], acc[mi][3]);
            }
        }
        __syncthreads();

        if (half == 0) {
#pragma unroll
            for (int mi = 0; mi < 4; mi++) {
                ulonglong2 q0 = pp[2 * mi], q1 = pp[2 * mi + 1];
                add2(acc[mi][0], q0.x); add2(acc[mi][1], q0.y);
                add2(acc[mi][2], q1.x); add2(acc[mi][3], q1.y);
            }

            // ---- epilogue ----
            float* hout = (LAYER == 0)
                ? g_h0s + (size_t)t * BB * HH
                : g_h1 + (size_t)(t & 3) * BB * HH;
#pragma unroll
            for (int mi = 0; mi < 4; mi++) {
                float i0, i1, f0, f1, gg0, gg1, o0, o1;
                upk2(i0, i1, acc[mi][0]);
                upk2(f0, f1, acc[mi][1]);
                upk2(gg0, gg1, acc[mi][2]);
                upk2(o0, o1, acc[mi][3]);
                i0 += gv[mi][0].x; i1 += gv[mi][0].y;
                f0 += gv[mi][1].x; f1 += gv[mi][1].y;
                gg0 += gv[mi][2].x; gg1 += gv[mi][2].y;
                o0 += gv[mi][3].x; o1 += gv[mi][3].y;

                float c0 = sigf(f0) * cst[mi].x + sigf(i0) * tanhf_(gg0);
                float c1 = sigf(f1) * cst[mi].y + sigf(i1) * tanhf_(gg1);
                cst[mi].x = c0; cst[mi].y = c1;
                float h0v = sigf(o0) * tanhf_(c0);
                float h1v = sigf(o1) * tanhf_(c1);

                int m = m0 + 4 * tmq + mi;
                __stcg((float2*)(hout + (size_t)m * HH + j0 + 2 * tj), make_float2(h0v, h1v));

                if (LAYER == 1 && t <= lastv[mi]) {
                    pool[mi].x = fmaxf(pool[mi].x, h0v);
                    pool[mi].y = fmaxf(pool[mi].y, h1v);
                }
            }
        }

        // ---- inter-step barrier: per-m-group, release-arrive + acquire-poll ----
        if (t != TT - 1) {
            __threadfence();                    // release: order h stores
            __syncthreads();
            if (tx == 0) bar_arrive_release(bar);
            if (half == 0) {
                // overlap: prefetch next step's gates while barrier settles
                const float* Gt = g_G + (size_t)(t + 1) * BB * G4;
#pragma unroll
                for (int mi = 0; mi < 4; mi++) {
                    const float* gr = Gt + (size_t)(m0 + 4 * tmq + mi) * G4 + j0 + 2 * tj;
#pragma unroll
                    for (int g = 0; g < 4; g++) gv[mi][g] = __ldcg((const float2*)(gr + g * 512));
                }
            }
            if (tx == 0) {
                unsigned target = 32u * (unsigned)(t + 1);
                while (bar_ld_acquire(bar) < target) { }
            }
            __syncthreads();
            __threadfence();                    // acquire for all reader threads
        }
    }

    if (LAYER == 1 && half == 0) {
#pragma unroll
        for (int mi = 0; mi < 4; mi++) {
            int m = m0 + 4 * tmq + mi;
            *(float2*)&g_pooled[m * HH + j0 + 2 * tj] = pool[mi];
        }
    }
}

// ---------------- final projection ----------------
__global__ void k_logits(const float* __restrict__ Wout, const float* __restrict__ bout,
                         float* __restrict__ out) {
    int b = blockIdx.x;
    int tx = threadIdx.x;
    float p[NCLS] = {0, 0, 0, 0, 0};
    for (int k = tx; k < HH; k += 128) {
        float v = g_pooled[b * HH + k];
#pragma unroll
        for (int c = 0; c < NCLS; c++) p[c] += v * Wout[c * HH + k];
    }
#pragma unroll
    for (int off = 16; off; off >>= 1)
#pragma unroll
        for (int c = 0; c < NCLS; c++) p[c] += __shfl_down_sync(0xffffffffu, p[c], off);
    __shared__ float red[4][NCLS];
    if ((tx & 31) == 0)
#pragma unroll
        for (int c = 0; c < NCLS; c++) red[tx >> 5][c] = p[c];
    __syncthreads();
    if (tx == 0) {
#pragma unroll
        for (int c = 0; c < NCLS; c++)
            out[b * NCLS + c] = red[0][c] + red[1][c] + red[2][c] + red[3][c] + bout[c];
    }
}

// ---------------- launch ----------------
extern "C" void kernel_launch(void* const* d_in, const int* in_sizes, int n_in,
                              void* d_out, int out_size) {
    (void)in_sizes; (void)n_in; (void)out_size;
    const int*   X      = (const int*)d_in[0];
    const float* emb    = (const float*)d_in[1];
    const float* W_ih0  = (const float*)d_in[2];
    const float* W_hh0  = (const float*)d_in[3];
    const float* b0     = (const float*)d_in[4];
    const float* W_ih1  = (const float*)d_in[5];
    const float* W_hh1  = (const float*)d_in[6];
    const float* b1     = (const float*)d_in[7];
    const float* W_out  = (const float*)d_in[8];
    const float* b_out  = (const float*)d_in[9];
    float* out = (float*)d_out;

    cudaFuncSetAttribute(k_recur<0>, cudaFuncAttributeMaxDynamicSharedMemorySize, RS_SMEM);
    cudaFuncSetAttribute(k_recur<1>, cudaFuncAttributeMaxDynamicSharedMemorySize, RS_SMEM);

    // order keeps k_recur<0> in the ncu capture slot
    k_padw0<<<(G4 * EP + 255) / 256, 256>>>(W_ih0);              // 1 (also zeroes barriers)
    k_gather<<<MROWS, 128>>>(X, emb);                            // 2
    k_gemm<<<dim3(16, 400), 256>>>(nullptr, b0, 0);              // 3
    k_recur<0><<<dim3(32, 4), RTHREADS, RS_SMEM>>>(W_hh0);       // 4  <- capture target
    k_last<<<1, 256>>>(X);                                       // 5
    k_gemm<<<dim3(16, 400), 256>>>(W_ih1, b1, 1);                // 6
    k_recur<1><<<dim3(32, 4), RTHREADS, RS_SMEM>>>(W_hh1);       // 7
    k_logits<<<BB, 128>>>(W_out, b_out, out);                    // 8
}

// round 12
// speedup vs baseline: 2.8312x; 1.7799x over previous
#include <cuda_runtime.h>
#include <cuda_bf16.h>
#include <math.h>
#include <float.h>
#include <stdint.h>

#define BB 256
#define TT 200
#define EE 100
#define EP 112
#define HH 512
#define G4 2048
#define NCLS 5
#define VV 50000
#define MROWS (TT*BB)
#define KP 1024                    // W split cols: [hi(512) | lo(512)]

// ---------------- static device scratch ----------------
__device__ float g_xe[(size_t)MROWS * EP];
__device__ float g_W0p[(size_t)G4 * EP];
__device__ float g_G[(size_t)MROWS * G4];
__device__ float g_h0s[(size_t)MROWS * HH];            // layer0 h archive (fp32, feeds G1 GEMM)
__device__ __align__(16) __nv_bfloat16 g_Wb0[(size_t)G4 * KP];
__device__ __align__(16) __nv_bfloat16 g_Wb1[(size_t)G4 * KP];
__device__ __align__(16) __nv_bfloat16 g_hb[4][2][BB * HH];   // h ring [t&3][hi/lo]
__device__ float g_pooled[BB * HH];
__device__ int   g_last[BB];
__device__ unsigned g_bar[2][4];                        // [layer][m-group]

// ---------------- packed f32x2 helpers (k_gemm) ----------------
__device__ __forceinline__ unsigned long long pk2(float lo, float hi) {
    unsigned long long r;
    asm("mov.b64 %0, {%1,%2};" : "=l"(r) : "f"(lo), "f"(hi));
    return r;
}
__device__ __forceinline__ void upk2(float& lo, float& hi, unsigned long long v) {
    asm("mov.b64 {%0,%1}, %2;" : "=f"(lo), "=f"(hi) : "l"(v));
}
__device__ __forceinline__ void fma2(unsigned long long& d, unsigned long long a, unsigned long long b) {
    asm("fma.rn.f32x2 %0, %1, %2, %0;" : "+l"(d) : "l"(a), "l"(b));
}
__device__ __forceinline__ void bar_arrive_release(unsigned* p) {
    unsigned dummy;
    asm volatile("atom.release.gpu.global.add.u32 %0, [%1], 1;"
                 : "=r"(dummy) : "l"(p) : "memory");
}
__device__ __forceinline__ unsigned bar_ld_acquire(const unsigned* p) {
    unsigned v;
    asm volatile("ld.acquire.gpu.global.u32 %0, [%1];" : "=r"(v) : "l"(p) : "memory");
    return v;
}
__device__ __forceinline__ float sigf(float x)   { return 1.0f / (1.0f + __expf(-x)); }
__device__ __forceinline__ float tanhf_(float x) { return 2.0f / (1.0f + __expf(-2.0f * x)) - 1.0f; }

__device__ __forceinline__ uint32_t smem_u32(const void* p) {
    uint32_t a;
    asm("{ .reg .u64 t; cvta.to.shared.u64 t, %1; cvt.u32.u64 %0, t; }" : "=r"(a) : "l"(p));
    return a;
}
__device__ __forceinline__ void ldsm4(uint32_t* r, uint32_t a) {
    asm volatile("ldmatrix.sync.aligned.m8n8.x4.shared.b16 {%0,%1,%2,%3}, [%4];"
        : "=r"(r[0]), "=r"(r[1]), "=r"(r[2]), "=r"(r[3]) : "r"(a));
}
__device__ __forceinline__ void ldsm2(uint32_t* r, uint32_t a) {
    asm volatile("ldmatrix.sync.aligned.m8n8.x2.shared.b16 {%0,%1}, [%2];"
        : "=r"(r[0]), "=r"(r[1]) : "r"(a));
}
__device__ __forceinline__ void mma16816(float* d, const uint32_t* a, const uint32_t* b) {
    asm volatile("mma.sync.aligned.m16n8k16.row.col.f32.bf16.bf16.f32 "
        "{%0,%1,%2,%3}, {%4,%5,%6,%7}, {%8,%9}, {%0,%1,%2,%3};"
        : "+f"(d[0]), "+f"(d[1]), "+f"(d[2]), "+f"(d[3])
        : "r"(a[0]), "r"(a[1]), "r"(a[2]), "r"(a[3]), "r"(b[0]), "r"(b[1]));
}
__device__ __forceinline__ unsigned pack_bf16(float f0, float f1) {
    unsigned r;
    asm("cvt.rn.bf16x2.f32 %0, %1, %2;" : "=r"(r) : "f"(f1), "f"(f0));
    return r;
}

// ---------------- prep kernels ----------------
__global__ void k_last(const int* __restrict__ X) {
    int b = threadIdx.x;
    if (b < BB) {
        int l = -1;
        for (int t = 0; t < TT; t++)
            if (X[b * TT + t] != VV) l = t;
        g_last[b] = l;
    }
}

#define P0 (G4 * EP)
#define CW (G4 * HH)
__global__ void k_prep(const float* __restrict__ W0,
                       const float* __restrict__ Whh0,
                       const float* __restrict__ Whh1) {
    int idx = blockIdx.x * blockDim.x + threadIdx.x;
    if (idx < 8) ((unsigned*)g_bar)[idx] = 0u;
    if (idx < P0) {
        int n = idx / EP, k = idx % EP;
        g_W0p[idx] = (k < EE) ? W0[n * EE + k] : 0.0f;
    } else if (idx < P0 + 2 * CW) {
        int i = idx - P0;
        const float* Ws = (i < CW) ? Whh0 : Whh1;
        __nv_bfloat16* Wb = (i < CW) ? g_Wb0 : g_Wb1;
        if (i >= CW) i -= CW;
        int n = i >> 9, k = i & 511;
        float w = Ws[n * HH + k];
        __nv_bfloat16 hi = __float2bfloat16(w);
        __nv_bfloat16 lo = __float2bfloat16(w - __bfloat162float(hi));
        __nv_bfloat16* dst = Wb + (size_t)n * KP;
        dst[k] = hi; dst[512 + k] = lo;
    }
}

__global__ void k_gather(const int* __restrict__ X, const float* __restrict__ emb) {
    int row = blockIdx.x;
    int t = row / BB, b = row % BB;
    int tok = X[b * TT + t];
    const float* src = emb + (size_t)tok * EE;
    for (int e = threadIdx.x; e < EP; e += blockDim.x)
        g_xe[(size_t)row * EP + e] = (e < EE) ? src[e] : 0.0f;
}

// ---------------- input GEMM (unchanged, proven) ----------------
__global__ void __launch_bounds__(256) k_gemm(const float* __restrict__ Wihp,
                                              const float* __restrict__ bias,
                                              int which) {
    const float* A; const float* W; int K;
    if (which == 0) { A = g_xe;  W = g_W0p; K = EP; }
    else            { A = g_h0s; W = Wihp;  K = HH; }
    float* C = g_G;

    __shared__ float As[16][132];
    __shared__ float Bs[16][132];

    int m0 = blockIdx.y * 128, n0 = blockIdx.x * 128;
    int tx = threadIdx.x;
    int tn = tx & 15, tm = tx >> 4;

    unsigned long long acc[8][4];
#pragma unroll
    for (int i = 0; i < 8; i++)
#pragma unroll
        for (int j = 0; j < 4; j++) acc[i][j] = 0ull;

    int nt = K / 16;
    float4 va[2], vb[2];
#pragma unroll
    for (int i = 0; i < 2; i++) {
        int id = i * 256 + tx;
        int row = id >> 2, kq = (id & 3) * 4;
        va[i] = *(const float4*)(A + (size_t)(m0 + row) * K + kq);
        vb[i] = *(const float4*)(W + (size_t)(n0 + row) * K + kq);
    }

#pragma unroll 1
    for (int kt = 0; kt < nt; kt++) {
        float4 nva[2], nvb[2];
        if (kt + 1 < nt) {
            int k0n = (kt + 1) * 16;
#pragma unroll
            for (int i = 0; i < 2; i++) {
                int id = i * 256 + tx;
                int row = id >> 2, kq = (id & 3) * 4;
                nva[i] = *(const float4*)(A + (size_t)(m0 + row) * K + k0n + kq);
                nvb[i] = *(const float4*)(W + (size_t)(n0 + row) * K + k0n + kq);
            }
        }
#pragma unroll
        for (int i = 0; i < 2; i++) {
            int id = i * 256 + tx;
            int row = id >> 2, kq = (id & 3) * 4;
            As[kq + 0][row] = va[i].x; As[kq + 1][row] = va[i].y;
            As[kq + 2][row] = va[i].z; As[kq + 3][row] = va[i].w;
            Bs[kq + 0][row] = vb[i].x; Bs[kq + 1][row] = vb[i].y;
            Bs[kq + 2][row] = vb[i].z; Bs[kq + 3][row] = vb[i].w;
        }
        __syncthreads();
#pragma unroll
        for (int k = 0; k < 16; k++) {
            float4 a0 = *(const float4*)&As[k][tm * 4];
            float4 a1 = *(const float4*)&As[k][64 + tm * 4];
            unsigned long long pb[4];
            pb[0] = *(const unsigned long long*)&Bs[k][tn * 4];
            pb[1] = *(const unsigned long long*)&Bs[k][tn * 4 + 2];
            pb[2] = *(const unsigned long long*)&Bs[k][64 + tn * 4];
            pb[3] = *(const unsigned long long*)&Bs[k][64 + tn * 4 + 2];
            float am[8] = { a0.x, a0.y, a0.z, a0.w, a1.x, a1.y, a1.z, a1.w };
#pragma unroll
            for (int mi = 0; mi < 8; mi++) {
                unsigned long long pa = pk2(am[mi], am[mi]);
#pragma unroll
                for (int np = 0; np < 4; np++) fma2(acc[mi][np], pa, pb[np]);
            }
        }
        __syncthreads();
#pragma unroll
        for (int i = 0; i < 2; i++) { va[i] = nva[i]; vb[i] = nvb[i]; }
    }

    float4 bi0 = *(const float4*)(bias + n0 + tn * 4);
    float4 bi1 = *(const float4*)(bias + n0 + 64 + tn * 4);
#pragma unroll
    for (int mi = 0; mi < 8; mi++) {
        int row = m0 + ((mi < 4) ? (tm * 4 + mi) : (64 + tm * 4 + mi - 4));
        float4 o;
        upk2(o.x, o.y, acc[mi][0]); upk2(o.z, o.w, acc[mi][1]);
        o.x += bi0.x; o.y += bi0.y; o.z += bi0.z; o.w += bi0.w;
        *(float4*)(C + (size_t)row * G4 + n0 + tn * 4) = o;
        upk2(o.x, o.y, acc[mi][2]); upk2(o.z, o.w, acc[mi][3]);
        o.x += bi1.x; o.y += bi1.y; o.z += bi1.z; o.w += bi1.w;
        *(float4*)(C + (size_t)row * G4 + n0 + 64 + tn * 4) = o;
    }
}

// ---------------- mma.sync persistent recurrence ----------------
// grid (32 j-tiles, 4 m-groups) = 128 CTAs, 256 threads.
// CTA tile: 64m x 64n(4g x 16j). K' = 1536 split-bf16 via [hhi*Whi + hhi*Wlo + hlo*Whi].
// W slab smem-resident [64n][1024k] bf16; A staged per step in 8 x 16KB chunks.
#define ABUF_OFF 0
#define ABUF_SZ  16384
#define WS_OFF   32768
#define GB_OFF   163840
#define GB_STRIDE 68
#define RS_SMEM  181504

template<int LAYER>
__global__ void __launch_bounds__(256) k_recur() {
    extern __shared__ char smem[];
    uint32_t sbase = smem_u32(smem);
    float* Gbuf = (float*)(smem + GB_OFF);
    int tx = threadIdx.x;
    int wid = tx >> 5, lane = tx & 31;
    int wm = wid >> 2, wn = wid & 3;          // warp tile: 32m x 16n
    int j0 = blockIdx.x * 16;
    int m0 = blockIdx.y * 64;
    unsigned* bar = &g_bar[LAYER][blockIdx.y];
    const __nv_bfloat16* Wb = LAYER ? g_Wb1 : g_Wb0;

    // ---- stage W slab once: Ws[n][1024], n = g*16+jj, swizzled c16 ^ (n&7) ----
    for (int u = tx; u < 8192; u += 256) {
        int n = u >> 7, c16 = u & 127;
        int wrow = (n >> 4) * HH + j0 + (n & 15);
        uint4 v = *(const uint4*)(Wb + (size_t)wrow * KP + c16 * 8);
        *(uint4*)(smem + WS_OFF + n * 2048 + ((c16 ^ (n & 7)) << 4)) = v;
    }
    __syncthreads();

    // ldmatrix address precomputation
    int Arow = wm * 32 + (lane & 15);
    uint32_t AoffRow = (uint32_t)Arow * 256;
    int Asw = Arow & 7;
    int Alsel = lane >> 4;
    int Bn = wn * 16 + (lane & 7);
    uint32_t Boff0 = sbase + WS_OFF + (uint32_t)Bn * 2048;
    int Bsw = Bn & 7;
    int Blsel = (lane >> 3) & 1;

    // epilogue ownership: thread -> m row (tx>>2), 4 j's ((tx&3)*4..+3)
    int mym = tx >> 2, jq = tx & 3;
    size_t hoff = (size_t)(m0 + mym) * HH + j0 + jq * 4;
    float cst4[4] = {0.f, 0.f, 0.f, 0.f};
    float pool4[4] = {-FLT_MAX, -FLT_MAX, -FLT_MAX, -FLT_MAX};
    int lastv = (LAYER == 1) ? g_last[m0 + mym] : 0;
    float4 gvv[4];
    {
        const float* gr = g_G + (size_t)(m0 + mym) * G4 + j0 + jq * 4;
#pragma unroll
        for (int g = 0; g < 4; g++) gvv[g] = __ldcg((const float4*)(gr + g * 512));
    }

    for (int t = 0; t < TT; t++) {
        if (t > 0) {
            int ring = (t - 1) & 3;
            float d[2][2][4];
#pragma unroll
            for (int a = 0; a < 2; a++)
#pragma unroll
                for (int b = 0; b < 2; b++)
#pragma unroll
                    for (int q = 0; q < 4; q++) d[a][b][q] = 0.f;

            // prefetch chunk 0 (hi plane, k 0..127)
            uint4 pv[4];
            {
                const __nv_bfloat16* pl = g_hb[ring][0];
#pragma unroll
                for (int i = 0; i < 4; i++) {
                    int u = i * 256 + tx, r = u >> 4, c16 = u & 15;
                    pv[i] = __ldcg((const uint4*)(pl + (size_t)(m0 + r) * HH + c16 * 8));
                }
            }
#pragma unroll 1
            for (int c = 0; c < 8; c++) {
                char* Ab = smem + ABUF_OFF + (c & 1) * ABUF_SZ;
#pragma unroll
                for (int i = 0; i < 4; i++) {
                    int u = i * 256 + tx, r = u >> 4, c16 = u & 15;
                    *(uint4*)(Ab + r * 256 + ((c16 ^ (r & 7)) << 4)) = pv[i];
                }
                __syncthreads();
                if (c < 7) {
                    const __nv_bfloat16* pl = g_hb[ring][(c + 1) >= 4 ? 1 : 0];
                    int ck = ((c + 1) & 3) * 128;
#pragma unroll
                    for (int i = 0; i < 4; i++) {
                        int u = i * 256 + tx, r = u >> 4, c16 = u & 15;
                        pv[i] = __ldcg((const uint4*)(pl + (size_t)(m0 + r) * HH + ck + c16 * 8));
                    }
                }
                uint32_t AbufBase = sbase + ABUF_OFF + (c & 1) * ABUF_SZ + AoffRow;
#pragma unroll
                for (int ks = 0; ks < 8; ks++) {
                    uint32_t a0[4], a1[4];
                    uint32_t aoff = (uint32_t)(((ks * 2 + Alsel) ^ Asw) << 4);
                    ldsm4(a0, AbufBase + aoff);
                    ldsm4(a1, AbufBase + 16 * 256 + aoff);
                    int c16h = (c & 3) * 16 + ks * 2;
                    {   // term vs Whi
                        uint32_t b0[2], b1[2];
                        uint32_t boff = (uint32_t)((((c16h + Blsel)) ^ Bsw) << 4);
                        ldsm2(b0, Boff0 + boff);
                        ldsm2(b1, Boff0 + 8 * 2048 + boff);
                        mma16816(d[0][0], a0, b0); mma16816(d[0][1], a0, b1);
                        mma16816(d[1][0], a1, b0); mma16816(d[1][1], a1, b1);
                    }
                    if (c < 4) {   // A-hi also vs Wlo (c16 + 64)
                        uint32_t b0[2], b1[2];
                        uint32_t boff = (uint32_t)((((c16h + 64 + Blsel)) ^ Bsw) << 4);
                        ldsm2(b0, Boff0 + boff);
                        ldsm2(b1, Boff0 + 8 * 2048 + boff);
                        mma16816(d[0][0], a0, b0); mma16816(d[0][1], a0, b1);
                        mma16816(d[1][0], a1, b0); mma16816(d[1][1], a1, b1);
                    }
                }
                __syncthreads();
            }
            // store C fragments to gate buffer
            {
                int row = wm * 32 + (lane >> 2);
                int col = wn * 16 + (lane & 3) * 2;
#pragma unroll
                for (int mi = 0; mi < 2; mi++)
#pragma unroll
                    for (int ni = 0; ni < 2; ni++) {
                        int rr = row + mi * 16, cc = col + ni * 8;
                        *(float2*)&Gbuf[rr * GB_STRIDE + cc] = make_float2(d[mi][ni][0], d[mi][ni][1]);
                        *(float2*)&Gbuf[(rr + 8) * GB_STRIDE + cc] = make_float2(d[mi][ni][2], d[mi][ni][3]);
                    }
            }
            __syncthreads();
        }

        // ---- epilogue ----
        {
            float gg[4][4];
#pragma unroll
            for (int g = 0; g < 4; g++) {
                if (t > 0) {
                    float4 q = *(const float4*)&Gbuf[mym * GB_STRIDE + g * 16 + jq * 4];
                    gg[g][0] = q.x + ((const float*)&gvv[g])[0];
                    gg[g][1] = q.y + ((const float*)&gvv[g])[1];
                    gg[g][2] = q.z + ((const float*)&gvv[g])[2];
                    gg[g][3] = q.w + ((const float*)&gvv[g])[3];
                } else {
                    gg[g][0] = ((const float*)&gvv[g])[0];
                    gg[g][1] = ((const float*)&gvv[g])[1];
                    gg[g][2] = ((const float*)&gvv[g])[2];
                    gg[g][3] = ((const float*)&gvv[g])[3];
                }
            }
            float h4[4];
#pragma unroll
            for (int j = 0; j < 4; j++) {
                float cc = sigf(gg[1][j]) * cst4[j] + sigf(gg[0][j]) * tanhf_(gg[2][j]);
                cst4[j] = cc;
                h4[j] = sigf(gg[3][j]) * tanhf_(cc);
                if (LAYER == 1 && t <= lastv) pool4[j] = fmaxf(pool4[j], h4[j]);
            }
            // write h ring (bf16 hi + residual lo)
            unsigned hw[2], lw[2];
#pragma unroll
            for (int q = 0; q < 2; q++) {
                float h0 = h4[2 * q], h1 = h4[2 * q + 1];
                __nv_bfloat16 b0 = __float2bfloat16(h0), b1 = __float2bfloat16(h1);
                float r0 = h0 - __bfloat162float(b0), r1 = h1 - __bfloat162float(b1);
                hw[q] = pack_bf16(__bfloat162float(b0), __bfloat162float(b1));
                lw[q] = pack_bf16(r0, r1);
            }
            int wring = t & 3;
            __stcg((uint2*)&g_hb[wring][0][hoff], make_uint2(hw[0], hw[1]));
            __stcg((uint2*)&g_hb[wring][1][hoff], make_uint2(lw[0], lw[1]));
            if (LAYER == 0)
                __stcg((float4*)(g_h0s + (size_t)t * BB * HH + hoff),
                       make_float4(h4[0], h4[1], h4[2], h4[3]));
        }

        // ---- inter-step barrier: per-m-group, release-arrive + acquire-poll ----
        if (t != TT - 1) {
            __threadfence();
            __syncthreads();
            if (tx == 0) bar_arrive_release(bar);
            {
                const float* gr = g_G + (size_t)(t + 1) * BB * G4
                                + (size_t)(m0 + mym) * G4 + j0 + jq * 4;
#pragma unroll
                for (int g = 0; g < 4; g++) gvv[g] = __ldcg((const float4*)(gr + g * 512));
            }
            if (tx == 0) {
                unsigned target = 32u * (unsigned)(t + 1);
                while (bar_ld_acquire(bar) < target) { }
            }
            __syncthreads();
            __threadfence();
        }
    }

    if (LAYER == 1) {
        *(float4*)&g_pooled[hoff] = make_float4(pool4[0], pool4[1], pool4[2], pool4[3]);
    }
}

// ---------------- final projection ----------------
__global__ void k_logits(const float* __restrict__ Wout, const float* __restrict__ bout,
                         float* __restrict__ out) {
    int b = blockIdx.x;
    int tx = threadIdx.x;
    float p[NCLS] = {0, 0, 0, 0, 0};
    for (int k = tx; k < HH; k += 128) {
        float v = g_pooled[b * HH + k];
#pragma unroll
        for (int c = 0; c < NCLS; c++) p[c] += v * Wout[c * HH + k];
    }
#pragma unroll
    for (int off = 16; off; off >>= 1)
#pragma unroll
        for (int c = 0; c < NCLS; c++) p[c] += __shfl_down_sync(0xffffffffu, p[c], off);
    __shared__ float red[4][NCLS];
    if ((tx & 31) == 0)
#pragma unroll
        for (int c = 0; c < NCLS; c++) red[tx >> 5][c] = p[c];
    __syncthreads();
    if (tx == 0) {
#pragma unroll
        for (int c = 0; c < NCLS; c++)
            out[b * NCLS + c] = red[0][c] + red[1][c] + red[2][c] + red[3][c] + bout[c];
    }
}

// ---------------- launch ----------------
extern "C" void kernel_launch(void* const* d_in, const int* in_sizes, int n_in,
                              void* d_out, int out_size) {
    (void)in_sizes; (void)n_in; (void)out_size;
    const int*   X      = (const int*)d_in[0];
    const float* emb    = (const float*)d_in[1];
    const float* W_ih0  = (const float*)d_in[2];
    const float* W_hh0  = (const float*)d_in[3];
    const float* b0     = (const float*)d_in[4];
    const float* W_ih1  = (const float*)d_in[5];
    const float* W_hh1  = (const float*)d_in[6];
    const float* b1     = (const float*)d_in[7];
    const float* W_out  = (const float*)d_in[8];
    const float* b_out  = (const float*)d_in[9];
    float* out = (float*)d_out;

    cudaFuncSetAttribute(k_recur<0>, cudaFuncAttributeMaxDynamicSharedMemorySize, RS_SMEM);
    cudaFuncSetAttribute(k_recur<1>, cudaFuncAttributeMaxDynamicSharedMemorySize, RS_SMEM);

    int prep_items = 8 + P0 + 2 * CW;
    // order keeps k_recur<0> in the ncu capture slot (launch 4)
    k_prep<<<(prep_items + 255) / 256, 256>>>(W_ih0, W_hh0, W_hh1);    // 1
    k_gather<<<MROWS, 128>>>(X, emb);                                   // 2
    k_gemm<<<dim3(16, 400), 256>>>(nullptr, b0, 0);                     // 3
    k_recur<0><<<dim3(32, 4), 256, RS_SMEM>>>();                        // 4  <- capture target
    k_last<<<1, 256>>>(X);                                              // 5
    k_gemm<<<dim3(16, 400), 256>>>(W_ih1, b1, 1);                       // 6
    k_recur<1><<<dim3(32, 4), 256, RS_SMEM>>>();                        // 7
    k_logits<<<BB, 128>>>(W_out, b_out, out);                           // 8
}

// round 14
// speedup vs baseline: 3.5284x; 1.2463x over previous
#include <cuda_runtime.h>
#include <cuda_bf16.h>
#include <math.h>
#include <float.h>
#include <stdint.h>

#define BB 256
#define TT 200
#define EE 100
#define EP 112
#define HH 512
#define G4 2048
#define NCLS 5
#define VV 50000
#define MROWS (TT*BB)
#define KP 1024                    // split cols: [hi(512) | lo(512)]

// ---------------- static device scratch ----------------
__device__ float g_xe[(size_t)MROWS * EP];
__device__ float g_W0p[(size_t)G4 * EP];
__device__ float g_G[(size_t)MROWS * G4];
__device__ __align__(16) __nv_bfloat16 g_h0b[2][(size_t)MROWS * HH];  // layer0 h archive hi/lo
__device__ __align__(16) __nv_bfloat16 g_Wb0[(size_t)G4 * KP];        // W_hh0 split
__device__ __align__(16) __nv_bfloat16 g_Wb1[(size_t)G4 * KP];        // W_hh1 split
__device__ __align__(16) __nv_bfloat16 g_Wib[(size_t)G4 * KP];        // W_ih1 split
__device__ __align__(16) __nv_bfloat16 g_hb[4][2][BB * HH];           // h ring [t&3][hi/lo]
__device__ float g_pooled[BB * HH];
__device__ int   g_last[BB];
__device__ unsigned g_bar[2][4];

// ---------------- helpers ----------------
__device__ __forceinline__ unsigned long long pk2(float lo, float hi) {
    unsigned long long r;
    asm("mov.b64 %0, {%1,%2};" : "=l"(r) : "f"(lo), "f"(hi));
    return r;
}
__device__ __forceinline__ void upk2(float& lo, float& hi, unsigned long long v) {
    asm("mov.b64 {%0,%1}, %2;" : "=f"(lo), "=f"(hi) : "l"(v));
}
__device__ __forceinline__ void fma2(unsigned long long& d, unsigned long long a, unsigned long long b) {
    asm("fma.rn.f32x2 %0, %1, %2, %0;" : "+l"(d) : "l"(a), "l"(b));
}
__device__ __forceinline__ void bar_arrive_release(unsigned* p) {
    unsigned dummy;
    asm volatile("atom.release.gpu.global.add.u32 %0, [%1], 1;"
                 : "=r"(dummy) : "l"(p) : "memory");
}
__device__ __forceinline__ unsigned bar_ld_acquire(const unsigned* p) {
    unsigned v;
    asm volatile("ld.acquire.gpu.global.u32 %0, [%1];" : "=r"(v) : "l"(p) : "memory");
    return v;
}
__device__ __forceinline__ float sigf(float x)   { return 1.0f / (1.0f + __expf(-x)); }
__device__ __forceinline__ float tanhf_(float x) { return 2.0f / (1.0f + __expf(-2.0f * x)) - 1.0f; }

__device__ __forceinline__ uint32_t smem_u32(const void* p) {
    uint32_t a;
    asm("{ .reg .u64 t; cvta.to.shared.u64 t, %1; cvt.u32.u64 %0, t; }" : "=r"(a) : "l"(p));
    return a;
}
__device__ __forceinline__ void ldsm4(uint32_t* r, uint32_t a) {
    asm volatile("ldmatrix.sync.aligned.m8n8.x4.shared.b16 {%0,%1,%2,%3}, [%4];"
        : "=r"(r[0]), "=r"(r[1]), "=r"(r[2]), "=r"(r[3]) : "r"(a));
}
__device__ __forceinline__ void mma16816(float* d, const uint32_t* a, const uint32_t* b) {
    asm volatile("mma.sync.aligned.m16n8k16.row.col.f32.bf16.bf16.f32 "
        "{%0,%1,%2,%3}, {%4,%5,%6,%7}, {%8,%9}, {%0,%1,%2,%3};"
        : "+f"(d[0]), "+f"(d[1]), "+f"(d[2]), "+f"(d[3])
        : "r"(a[0]), "r"(a[1]), "r"(a[2]), "r"(a[3]), "r"(b[0]), "r"(b[1]));
}
__device__ __forceinline__ unsigned pack_bf16(float f0, float f1) {
    unsigned r;
    asm("cvt.rn.bf16x2.f32 %0, %1, %2;" : "=r"(r) : "f"(f1), "f"(f0));
    return r;
}
__device__ __forceinline__ void cp16(uint32_t sa, const void* ga) {
    asm volatile("cp.async.cg.shared.global [%0], [%1], 16;" :: "r"(sa), "l"(ga) : "memory");
}
#define CP_COMMIT() asm volatile("cp.async.commit_group;" ::: "memory")
#define CP_WAIT(n)  asm volatile("cp.async.wait_group %0;" :: "n"(n) : "memory")

// ---------------- prep kernels ----------------
__global__ void k_last(const int* __restrict__ X) {
    int b = threadIdx.x;
    if (b < BB) {
        int l = -1;
        for (int t = 0; t < TT; t++)
            if (X[b * TT + t] != VV) l = t;
        g_last[b] = l;
    }
}

#define P0 (G4 * EP)
#define CW (G4 * HH)
__global__ void k_prep(const float* __restrict__ W0,
                       const float* __restrict__ Whh0,
                       const float* __restrict__ Whh1,
                       const float* __restrict__ Wih1) {
    int idx = blockIdx.x * blockDim.x + threadIdx.x;
    if (idx < 8) ((unsigned*)g_bar)[idx] = 0u;
    if (idx < P0) {
        int n = idx / EP, k = idx % EP;
        g_W0p[idx] = (k < EE) ? W0[n * EE + k] : 0.0f;
    } else if (idx < P0 + 3 * CW) {
        int i = idx - P0;
        const float* Ws;
        __nv_bfloat16* Wb;
        if (i < CW)            { Ws = Whh0; Wb = g_Wb0; }
        else if (i < 2 * CW)   { Ws = Whh1; Wb = g_Wb1; i -= CW; }
        else                   { Ws = Wih1; Wb = g_Wib; i -= 2 * CW; }
        int n = i >> 9, k = i & 511;
        float w = Ws[n * HH + k];
        __nv_bfloat16 hi = __float2bfloat16(w);
        __nv_bfloat16 lo = __float2bfloat16(w - __bfloat162float(hi));
        __nv_bfloat16* dst = Wb + (size_t)n * KP;
        dst[k] = hi; dst[512 + k] = lo;
    }
}

__global__ void k_gather(const int* __restrict__ X, const float* __restrict__ emb) {
    int row = blockIdx.x;
    int t = row / BB, b = row % BB;
    int tok = X[b * TT + t];
    const float* src = emb + (size_t)tok * EE;
    for (int e = threadIdx.x; e < EP; e += blockDim.x)
        g_xe[(size_t)row * EP + e] = (e < EE) ? src[e] : 0.0f;
}

// ---------------- embedding GEMM (fp32, K=112, proven) ----------------
__global__ void __launch_bounds__(256) k_gemm(const float* __restrict__ bias) {
    const float* A = g_xe; const float* W = g_W0p; const int K = EP;
    float* C = g_G;

    __shared__ float As[16][132];
    __shared__ float Bs[16][132];

    int m0 = blockIdx.y * 128, n0 = blockIdx.x * 128;
    int tx = threadIdx.x;
    int tn = tx & 15, tm = tx >> 4;

    unsigned long long acc[8][4];
#pragma unroll
    for (int i = 0; i < 8; i++)
#pragma unroll
        for (int j = 0; j < 4; j++) acc[i][j] = 0ull;

    int nt = K / 16;
    float4 va[2], vb[2];
#pragma unroll
    for (int i = 0; i < 2; i++) {
        int id = i * 256 + tx;
        int row = id >> 2, kq = (id & 3) * 4;
        va[i] = *(const float4*)(A + (size_t)(m0 + row) * K + kq);
        vb[i] = *(const float4*)(W + (size_t)(n0 + row) * K + kq);
    }

#pragma unroll 1
    for (int kt = 0; kt < nt; kt++) {
        float4 nva[2], nvb[2];
        if (kt + 1 < nt) {
            int k0n = (kt + 1) * 16;
#pragma unroll
            for (int i = 0; i < 2; i++) {
                int id = i * 256 + tx;
                int row = id >> 2, kq = (id & 3) * 4;
                nva[i] = *(const float4*)(A + (size_t)(m0 + row) * K + k0n + kq);
                nvb[i] = *(const float4*)(W + (size_t)(n0 + row) * K + k0n + kq);
            }
        }
#pragma unroll
        for (int i = 0; i < 2; i++) {
            int id = i * 256 + tx;
            int row = id >> 2, kq = (id & 3) * 4;
            As[kq + 0][row] = va[i].x; As[kq + 1][row] = va[i].y;
            As[kq + 2][row] = va[i].z; As[kq + 3][row] = va[i].w;
            Bs[kq + 0][row] = vb[i].x; Bs[kq + 1][row] = vb[i].y;
            Bs[kq + 2][row] = vb[i].z; Bs[kq + 3][row] = vb[i].w;
        }
        __syncthreads();
#pragma unroll
        for (int k = 0; k < 16; k++) {
            float4 a0 = *(const float4*)&As[k][tm * 4];
            float4 a1 = *(const float4*)&As[k][64 + tm * 4];
            unsigned long long pb[4];
            pb[0] = *(const unsigned long long*)&Bs[k][tn * 4];
            pb[1] = *(const unsigned long long*)&Bs[k][tn * 4 + 2];
            pb[2] = *(const unsigned long long*)&Bs[k][64 + tn * 4];
            pb[3] = *(const unsigned long long*)&Bs[k][64 + tn * 4 + 2];
            float am[8] = { a0.x, a0.y, a0.z, a0.w, a1.x, a1.y, a1.z, a1.w };
#pragma unroll
            for (int mi = 0; mi < 8; mi++) {
                unsigned long long pa = pk2(am[mi], am[mi]);
#pragma unroll
                for (int np = 0; np < 4; np++) fma2(acc[mi][np], pa, pb[np]);
            }
        }
        __syncthreads();
#pragma unroll
        for (int i = 0; i < 2; i++) { va[i] = nva[i]; vb[i] = nvb[i]; }
    }

    float4 bi0 = *(const float4*)(bias + n0 + tn * 4);
    float4 bi1 = *(const float4*)(bias + n0 + 64 + tn * 4);
#pragma unroll
    for (int mi = 0; mi < 8; mi++) {
        int row = m0 + ((mi < 4) ? (tm * 4 + mi) : (64 + tm * 4 + mi - 4));
        float4 o;
        upk2(o.x, o.y, acc[mi][0]); upk2(o.z, o.w, acc[mi][1]);
        o.x += bi0.x; o.y += bi0.y; o.z += bi0.z; o.w += bi0.w;
        *(float4*)(C + (size_t)row * G4 + n0 + tn * 4) = o;
        upk2(o.x, o.y, acc[mi][2]); upk2(o.z, o.w, acc[mi][3]);
        o.x += bi1.x; o.y += bi1.y; o.z += bi1.z; o.w += bi1.w;
        *(float4*)(C + (size_t)row * G4 + n0 + 64 + tn * 4) = o;
    }
}

// ---------------- layer-1 input GEMM: split-bf16 mma.sync ----------------
// C[51200, 2048] = h0 @ W_ih1^T + b1.  3 terms (Ahi*Whi, Ahi*Wlo, Alo*Whi).
// CTA 128m x 64n, 8 warps (4m x 2n of 32x32). cp.async 3-buffer pipeline.
#define GBF_AB 16384
#define GBF_BB 8192
#define GBF_BOFF (3 * GBF_AB)
#define GBF_SMEM (3 * GBF_AB + 3 * GBF_BB)

__global__ void __launch_bounds__(256) k_gemm_bf(const float* __restrict__ bias) {
    extern __shared__ char smem[];
    uint32_t sbase = smem_u32(smem);
    int tx = threadIdx.x;
    int wid = tx >> 5, lane = tx & 31;
    int wm = wid & 3, wn = wid >> 2;
    int n0 = blockIdx.x * 64;
    size_t mr0 = (size_t)blockIdx.y * 128;

    // ldsm addressing
    int Arow = wm * 32 + (lane & 15);
    uint32_t ArowOff = (uint32_t)Arow * 128;
    int Asw = Arow & 7, Alsel = lane >> 4;
    int Brow = wn * 32 + (lane & 7) + ((lane >> 4) << 3);
    int Bksel = (lane >> 3) & 1;
    uint32_t BrowOff0 = (uint32_t)Brow * 128;
    uint32_t BrowOff1 = (uint32_t)(Brow + 16) * 128;
    int Bsw0 = Brow & 7, Bsw1 = (Brow + 16) & 7;

    float d[2][4][4];
#pragma unroll
    for (int a = 0; a < 2; a++)
#pragma unroll
        for (int b = 0; b < 4; b++)
#pragma unroll
            for (int q = 0; q < 4; q++) d[a][b][q] = 0.f;

    // issue chunk it (term = it>>3, ch = it&7)
    auto issue = [&](int it) {
        int term = it >> 3, ch = it & 7;
        const __nv_bfloat16* Apl = g_h0b[term == 2 ? 1 : 0];
        int acol = ch * 64;
        int bc16 = ch * 8 + (term == 1 ? 64 : 0);
        uint32_t Ab = sbase + (uint32_t)(it % 3) * GBF_AB;
        uint32_t Bb = sbase + GBF_BOFF + (uint32_t)(it % 3) * GBF_BB;
#pragma unroll
        for (int i = 0; i < 4; i++) {
            int u = i * 256 + tx, r = u >> 3, c16 = u & 7;
            cp16(Ab + r * 128 + (((uint32_t)(c16 ^ (r & 7))) << 4),
                 Apl + (mr0 + r) * HH + acol + c16 * 8);
        }
#pragma unroll
        for (int i = 0; i < 2; i++) {
            int u = i * 256 + tx, n = u >> 3, c16 = u & 7;
            cp16(Bb + n * 128 + (((uint32_t)(c16 ^ (n & 7))) << 4),
                 g_Wib + (size_t)(n0 + n) * KP + (bc16 + c16) * 8);
        }
    };

    issue(0); CP_COMMIT();
    issue(1); CP_COMMIT();

#pragma unroll 1
    for (int it = 0; it < 24; it++) {
        if (it < 23) { CP_WAIT(1); } else { CP_WAIT(0); }
        __syncthreads();
        if (it + 2 < 24) { issue(it + 2); CP_COMMIT(); }
        uint32_t Ab = sbase + (uint32_t)(it % 3) * GBF_AB;
        uint32_t Bb = sbase + GBF_BOFF + (uint32_t)(it % 3) * GBF_BB;
#pragma unroll
        for (int ks = 0; ks < 4; ks++) {
            uint32_t a0[4], a1[4];
            uint32_t aoff = (uint32_t)(((ks * 2 + Alsel) ^ Asw) << 4);
            ldsm4(a0, Ab + ArowOff + aoff);
            ldsm4(a1, Ab + ArowOff + 2048 + aoff);     // FIX: +16 rows * 128B (was 4096)
            uint32_t b0[4], b1[4];
            ldsm4(b0, Bb + BrowOff0 + (uint32_t)(((ks * 2 + Bksel) ^ Bsw0) << 4));
            ldsm4(b1, Bb + BrowOff1 + (uint32_t)(((ks * 2 + Bksel) ^ Bsw1) << 4));
            mma16816(d[0][0], a0, b0); mma16816(d[0][1], a0, b0 + 2);
            mma16816(d[0][2], a0, b1); mma16816(d[0][3], a0, b1 + 2);
            mma16816(d[1][0], a1, b0); mma16816(d[1][1], a1, b0 + 2);
            mma16816(d[1][2], a1, b1); mma16816(d[1][3], a1, b1 + 2);
        }
        __syncthreads();
    }

    // epilogue: add bias, write g_G
    int r_l = lane >> 2, c_l = (lane & 3) * 2;
#pragma unroll
    for (int mi = 0; mi < 2; mi++)
#pragma unroll
        for (int ni = 0; ni < 4; ni++) {
            size_t row = mr0 + wm * 32 + mi * 16 + r_l;
            int col = n0 + wn * 32 + ni * 8 + c_l;
            float b0v = bias[col], b1v = bias[col + 1];
            *(float2*)(g_G + row * G4 + col) = make_float2(d[mi][ni][0] + b0v, d[mi][ni][1] + b1v);
            *(float2*)(g_G + (row + 8) * G4 + col) = make_float2(d[mi][ni][2] + b0v, d[mi][ni][3] + b1v);
        }
}

// ---------------- mma.sync persistent recurrence ----------------
// 128 CTAs (32 j-tiles x 4 m-groups), 256 threads.
// cp.async 4-buffer depth-3 staging; B loads via ldmatrix.x4 (16n per load).
#define ABUF_SZ  16384
#define WS_OFF   65536
#define GB_OFF   196608
#define GB_STRIDE 68
#define RS_SMEM  214016

template<int LAYER>
__global__ void __launch_bounds__(256) k_recur() {
    extern __shared__ char smem[];
    uint32_t sbase = smem_u32(smem);
    float* Gbuf = (float*)(smem + GB_OFF);
    int tx = threadIdx.x;
    int wid = tx >> 5, lane = tx & 31;
    int wm = wid >> 2, wn = wid & 3;          // warp tile: 32m x 16n
    int j0 = blockIdx.x * 16;
    int m0 = blockIdx.y * 64;
    unsigned* bar = &g_bar[LAYER][blockIdx.y];
    const __nv_bfloat16* Wb = LAYER ? g_Wb1 : g_Wb0;

    // ---- stage W slab once: Ws[n][1024], n = g*16+jj ----
    for (int u = tx; u < 8192; u += 256) {
        int n = u >> 7, c16 = u & 127;
        int wrow = (n >> 4) * HH + j0 + (n & 15);
        uint4 v = *(const uint4*)(Wb + (size_t)wrow * KP + c16 * 8);
        *(uint4*)(smem + WS_OFF + n * 2048 + ((c16 ^ (n & 7)) << 4)) = v;
    }
    __syncthreads();

    // ldsm addressing
    int Arow = wm * 32 + (lane & 15);
    uint32_t AoffRow = (uint32_t)Arow * 256;
    int Asw = Arow & 7, Alsel = lane >> 4;
    int Brow = wn * 16 + (lane & 7) + ((lane >> 4) << 3);
    uint32_t BrowBase = sbase + WS_OFF + (uint32_t)Brow * 2048;
    int Bsw = Brow & 7, Bksel = (lane >> 3) & 1;

    // epilogue ownership
    int mym = tx >> 2, jq = tx & 3;
    size_t hoff = (size_t)(m0 + mym) * HH + j0 + jq * 4;
    float cst4[4] = {0.f, 0.f, 0.f, 0.f};
    float pool4[4] = {-FLT_MAX, -FLT_MAX, -FLT_MAX, -FLT_MAX};
    int lastv = (LAYER == 1) ? g_last[m0 + mym] : 0;
    float4 gvv[4];
    {
        const float* gr = g_G + (size_t)(m0 + mym) * G4 + j0 + jq * 4;
#pragma unroll
        for (int g = 0; g < 4; g++) gvv[g] = __ldcg((const float4*)(gr + g * 512));
    }

    for (int t = 0; t < TT; t++) {
        if (t > 0) {
            int ring = (t - 1) & 3;
            float d[2][2][4];
#pragma unroll
            for (int a = 0; a < 2; a++)
#pragma unroll
                for (int b = 0; b < 2; b++)
#pragma unroll
                    for (int q = 0; q < 4; q++) d[a][b][q] = 0.f;

            auto issue = [&](int c) {
                const __nv_bfloat16* pl = g_hb[ring][c >> 2];
                int ck = (c & 3) * 128;
                uint32_t Ab = sbase + (uint32_t)(c & 3) * ABUF_SZ;
#pragma unroll
                for (int i = 0; i < 4; i++) {
                    int u = i * 256 + tx, r = u >> 4, c16 = u & 15;
                    cp16(Ab + r * 256 + (((uint32_t)(c16 ^ (r & 7))) << 4),
                         pl + (size_t)(m0 + r) * HH + ck + c16 * 8);
                }
            };
            issue(0); CP_COMMIT();
            issue(1); CP_COMMIT();
            issue(2); CP_COMMIT();

#pragma unroll 1
            for (int c = 0; c < 8; c++) {
                if (c < 6) { CP_WAIT(2); }
                else if (c == 6) { CP_WAIT(1); }
                else { CP_WAIT(0); }
                __syncthreads();
                if (c + 3 < 8) { issue(c + 3); CP_COMMIT(); }
                uint32_t AbufBase = sbase + (uint32_t)(c & 3) * ABUF_SZ + AoffRow;
#pragma unroll
                for (int ks = 0; ks < 8; ks++) {
                    uint32_t a0[4], a1[4];
                    uint32_t aoff = (uint32_t)(((ks * 2 + Alsel) ^ Asw) << 4);
                    ldsm4(a0, AbufBase + aoff);
                    ldsm4(a1, AbufBase + 16 * 256 + aoff);
                    int c16h = (c & 3) * 16 + ks * 2;
                    {   // term vs Whi
                        uint32_t bb[4];
                        ldsm4(bb, BrowBase + (uint32_t)((((c16h + Bksel)) ^ Bsw) << 4));
                        mma16816(d[0][0], a0, bb); mma16816(d[0][1], a0, bb + 2);
                        mma16816(d[1][0], a1, bb); mma16816(d[1][1], a1, bb + 2);
                    }
                    if (c < 4) {   // A-hi also vs Wlo
                        uint32_t bb[4];
                        ldsm4(bb, BrowBase + (uint32_t)((((c16h + 64 + Bksel)) ^ Bsw) << 4));
                        mma16816(d[0][0], a0, bb); mma16816(d[0][1], a0, bb + 2);
                        mma16816(d[1][0], a1, bb); mma16816(d[1][1], a1, bb + 2);
                    }
                }
            }
            __syncthreads();
            // store C fragments to gate buffer
            {
                int row = wm * 32 + (lane >> 2);
                int col = wn * 16 + (lane & 3) * 2;
#pragma unroll
                for (int mi = 0; mi < 2; mi++)
#pragma unroll
                    for (int ni = 0; ni < 2; ni++) {
                        int rr = row + mi * 16, cc = col + ni * 8;
                        *(float2*)&Gbuf[rr * GB_STRIDE + cc] = make_float2(d[mi][ni][0], d[mi][ni][1]);
                        *(float2*)&Gbuf[(rr + 8) * GB_STRIDE + cc] = make_float2(d[mi][ni][2], d[mi][ni][3]);
                    }
            }
            __syncthreads();
        }

        // ---- epilogue ----
        {
            float gg[4][4];
#pragma unroll
            for (int g = 0; g < 4; g++) {
                if (t > 0) {
                    float4 q = *(const float4*)&Gbuf[mym * GB_STRIDE + g * 16 + jq * 4];
                    gg[g][0] = q.x + ((const float*)&gvv[g])[0];
                    gg[g][1] = q.y + ((const float*)&gvv[g])[1];
                    gg[g][2] = q.z + ((const float*)&gvv[g])[2];
                    gg[g][3] = q.w + ((const float*)&gvv[g])[3];
                } else {
                    gg[g][0] = ((const float*)&gvv[g])[0];
                    gg[g][1] = ((const float*)&gvv[g])[1];
                    gg[g][2] = ((const float*)&gvv[g])[2];
                    gg[g][3] = ((const float*)&gvv[g])[3];
                }
            }
            float h4[4];
#pragma unroll
            for (int j = 0; j < 4; j++) {
                float cc = sigf(gg[1][j]) * cst4[j] + sigf(gg[0][j]) * tanhf_(gg[2][j]);
                cst4[j] = cc;
                h4[j] = sigf(gg[3][j]) * tanhf_(cc);
                if (LAYER == 1 && t <= lastv) pool4[j] = fmaxf(pool4[j], h4[j]);
            }
            unsigned hw[2], lw[2];
#pragma unroll
            for (int q = 0; q < 2; q++) {
                float h0 = h4[2 * q], h1 = h4[2 * q + 1];
                __nv_bfloat16 b0 = __float2bfloat16(h0), b1 = __float2bfloat16(h1);
                float r0 = h0 - __bfloat162float(b0), r1 = h1 - __bfloat162float(b1);
                hw[q] = pack_bf16(__bfloat162float(b0), __bfloat162float(b1));
                lw[q] = pack_bf16(r0, r1);
            }
            int wring = t & 3;
            __stcg((uint2*)&g_hb[wring][0][hoff], make_uint2(hw[0], hw[1]));
            __stcg((uint2*)&g_hb[wring][1][hoff], make_uint2(lw[0], lw[1]));
            if (LAYER == 0) {
                size_t aoff = (size_t)t * BB * HH + hoff;
                __stcg((uint2*)&g_h0b[0][aoff], make_uint2(hw[0], hw[1]));
                __stcg((uint2*)&g_h0b[1][aoff], make_uint2(lw[0], lw[1]));
            }
        }

        // ---- inter-step barrier ----
        if (t != TT - 1) {
            __threadfence();
            __syncthreads();
            if (tx == 0) bar_arrive_release(bar);
            {
                const float* gr = g_G + (size_t)(t + 1) * BB * G4
                                + (size_t)(m0 + mym) * G4 + j0 + jq * 4;
#pragma unroll
                for (int g = 0; g < 4; g++) gvv[g] = __ldcg((const float4*)(gr + g * 512));
            }
            if (tx == 0) {
                unsigned target = 32u * (unsigned)(t + 1);
                while (bar_ld_acquire(bar) < target) { }
            }
            __syncthreads();
            __threadfence();
        }
    }

    if (LAYER == 1) {
        *(float4*)&g_pooled[hoff] = make_float4(pool4[0], pool4[1], pool4[2], pool4[3]);
    }
}

// ---------------- final projection ----------------
__global__ void k_logits(const float* __restrict__ Wout, const float* __restrict__ bout,
                         float* __restrict__ out) {
    int b = blockIdx.x;
    int tx = threadIdx.x;
    float p[NCLS] = {0, 0, 0, 0, 0};
    for (int k = tx; k < HH; k += 128) {
        float v = g_pooled[b * HH + k];
#pragma unroll
        for (int c = 0; c < NCLS; c++) p[c] += v * Wout[c * HH + k];
    }
#pragma unroll
    for (int off = 16; off; off >>= 1)
#pragma unroll
        for (int c = 0; c < NCLS; c++) p[c] += __shfl_down_sync(0xffffffffu, p[c], off);
    __shared__ float red[4][NCLS];
    if ((tx & 31) == 0)
#pragma unroll
        for (int c = 0; c < NCLS; c++) red[tx >> 5][c] = p[c];
    __syncthreads();
    if (tx == 0) {
#pragma unroll
        for (int c = 0; c < NCLS; c++)
            out[b * NCLS + c] = red[0][c] + red[1][c] + red[2][c] + red[3][c] + bout[c];
    }
}

// ---------------- launch ----------------
extern "C" void kernel_launch(void* const* d_in, const int* in_sizes, int n_in,
                              void* d_out, int out_size) {
    (void)in_sizes; (void)n_in; (void)out_size;
    const int*   X      = (const int*)d_in[0];
    const float* emb    = (const float*)d_in[1];
    const float* W_ih0  = (const float*)d_in[2];
    const float* W_hh0  = (const float*)d_in[3];
    const float* b0     = (const float*)d_in[4];
    const float* W_ih1  = (const float*)d_in[5];
    const float* W_hh1  = (const float*)d_in[6];
    const float* b1     = (const float*)d_in[7];
    const float* W_out  = (const float*)d_in[8];
    const float* b_out  = (const float*)d_in[9];
    float* out = (float*)d_out;

    cudaFuncSetAttribute(k_recur<0>, cudaFuncAttributeMaxDynamicSharedMemorySize, RS_SMEM);
    cudaFuncSetAttribute(k_recur<1>, cudaFuncAttributeMaxDynamicSharedMemorySize, RS_SMEM);
    cudaFuncSetAttribute(k_gemm_bf, cudaFuncAttributeMaxDynamicSharedMemorySize, GBF_SMEM);

    int prep_items = 8 + P0 + 3 * CW;
    // order keeps k_recur<0> in the ncu capture slot (launch 4)
    k_prep<<<(prep_items + 255) / 256, 256>>>(W_ih0, W_hh0, W_hh1, W_ih1);  // 1
    k_gather<<<MROWS, 128>>>(X, emb);                                        // 2
    k_gemm<<<dim3(16, 400), 256>>>(b0);                                      // 3
    k_recur<0><<<dim3(32, 4), 256, RS_SMEM>>>();                             // 4  <- capture target
    k_last<<<1, 256>>>(X);                                                   // 5
    k_gemm_bf<<<dim3(32, 400), 256, GBF_SMEM>>>(b1);                         // 6
    k_recur<1><<<dim3(32, 4), 256, RS_SMEM>>>();                             // 7
    k_logits<<<BB, 128>>>(W_out, b_out, out);                                // 8
}

// round 16
// speedup vs baseline: 3.5373x; 1.0025x over previous
#include <cuda_runtime.h>
#include <cuda_bf16.h>
#include <math.h>
#include <float.h>
#include <stdint.h>

#define BB 256
#define TT 200
#define EE 100
#define EP 112
#define HH 512
#define G4 2048
#define NCLS 5
#define VV 50000
#define MROWS (TT*BB)
#define KP 1024                    // split cols: [hi(512) | lo(512)]

// ---------------- static device scratch ----------------
__device__ float g_xe[(size_t)MROWS * EP];
__device__ float g_W0p[(size_t)G4 * EP];
__device__ float g_G[(size_t)MROWS * G4];
__device__ __align__(16) __nv_bfloat16 g_h0b[2][(size_t)MROWS * HH];  // layer0 h archive hi/lo
__device__ __align__(16) __nv_bfloat16 g_Wb0[(size_t)G4 * KP];        // W_hh0 split
__device__ __align__(16) __nv_bfloat16 g_Wb1[(size_t)G4 * KP];        // W_hh1 split
__device__ __align__(16) __nv_bfloat16 g_Wib[(size_t)G4 * KP];        // W_ih1 split
__device__ __align__(16) __nv_bfloat16 g_hb[4][2][BB * HH];           // h ring [t&3][hi/lo]
__device__ float g_pooled[BB * HH];
__device__ int   g_last[BB];
__device__ unsigned g_bar[2][4];

// ---------------- helpers ----------------
__device__ __forceinline__ unsigned long long pk2(float lo, float hi) {
    unsigned long long r;
    asm("mov.b64 %0, {%1,%2};" : "=l"(r) : "f"(lo), "f"(hi));
    return r;
}
__device__ __forceinline__ void upk2(float& lo, float& hi, unsigned long long v) {
    asm("mov.b64 {%0,%1}, %2;" : "=f"(lo), "=f"(hi) : "l"(v));
}
__device__ __forceinline__ void fma2(unsigned long long& d, unsigned long long a, unsigned long long b) {
    asm("fma.rn.f32x2 %0, %1, %2, %0;" : "+l"(d) : "l"(a), "l"(b));
}
__device__ __forceinline__ void bar_arrive_release(unsigned* p) {
    unsigned dummy;
    asm volatile("atom.release.gpu.global.add.u32 %0, [%1], 1;"
                 : "=r"(dummy) : "l"(p) : "memory");
}
__device__ __forceinline__ unsigned bar_ld_acquire(const unsigned* p) {
    unsigned v;
    asm volatile("ld.acquire.gpu.global.u32 %0, [%1];" : "=r"(v) : "l"(p) : "memory");
    return v;
}
__device__ __forceinline__ float sigf(float x)   { return 1.0f / (1.0f + __expf(-x)); }
__device__ __forceinline__ float tanhf_(float x) { return 2.0f / (1.0f + __expf(-2.0f * x)) - 1.0f; }

__device__ __forceinline__ uint32_t smem_u32(const void* p) {
    uint32_t a;
    asm("{ .reg .u64 t; cvta.to.shared.u64 t, %1; cvt.u32.u64 %0, t; }" : "=r"(a) : "l"(p));
    return a;
}
__device__ __forceinline__ void ldsm4(uint32_t* r, uint32_t a) {
    asm volatile("ldmatrix.sync.aligned.m8n8.x4.shared.b16 {%0,%1,%2,%3}, [%4];"
        : "=r"(r[0]), "=r"(r[1]), "=r"(r[2]), "=r"(r[3]) : "r"(a));
}
__device__ __forceinline__ void mma16816(float* d, const uint32_t* a, const uint32_t* b) {
    asm volatile("mma.sync.aligned.m16n8k16.row.col.f32.bf16.bf16.f32 "
        "{%0,%1,%2,%3}, {%4,%5,%6,%7}, {%8,%9}, {%0,%1,%2,%3};"
        : "+f"(d[0]), "+f"(d[1]), "+f"(d[2]), "+f"(d[3])
        : "r"(a[0]), "r"(a[1]), "r"(a[2]), "r"(a[3]), "r"(b[0]), "r"(b[1]));
}
__device__ __forceinline__ unsigned pack_bf16(float f0, float f1) {
    unsigned r;
    asm("cvt.rn.bf16x2.f32 %0, %1, %2;" : "=r"(r) : "f"(f1), "f"(f0));
    return r;
}
__device__ __forceinline__ void cp16(uint32_t sa, const void* ga) {
    asm volatile("cp.async.cg.shared.global [%0], [%1], 16;" :: "r"(sa), "l"(ga) : "memory");
}
#define CP_COMMIT() asm volatile("cp.async.commit_group;" ::: "memory")
#define CP_WAIT(n)  asm volatile("cp.async.wait_group %0;" :: "n"(n) : "memory")

// ---------------- prep kernels ----------------
__global__ void k_last(const int* __restrict__ X) {
    int b = threadIdx.x;
    if (b < BB) {
        int l = -1;
        for (int t = 0; t < TT; t++)
            if (X[b * TT + t] != VV) l = t;
        g_last[b] = l;
    }
}

#define P0 (G4 * EP)
#define CW (G4 * HH)
__global__ void k_prep(const float* __restrict__ W0,
                       const float* __restrict__ Whh0,
                       const float* __restrict__ Whh1,
                       const float* __restrict__ Wih1) {
    int idx = blockIdx.x * blockDim.x + threadIdx.x;
    if (idx < 8) ((unsigned*)g_bar)[idx] = 0u;
    if (idx < P0) {
        int n = idx / EP, k = idx % EP;
        g_W0p[idx] = (k < EE) ? W0[n * EE + k] : 0.0f;
    } else if (idx < P0 + 3 * CW) {
        int i = idx - P0;
        const float* Ws;
        __nv_bfloat16* Wb;
        if (i < CW)            { Ws = Whh0; Wb = g_Wb0; }
        else if (i < 2 * CW)   { Ws = Whh1; Wb = g_Wb1; i -= CW; }
        else                   { Ws = Wih1; Wb = g_Wib; i -= 2 * CW; }
        int n = i >> 9, k = i & 511;
        float w = Ws[n * HH + k];
        __nv_bfloat16 hi = __float2bfloat16(w);
        __nv_bfloat16 lo = __float2bfloat16(w - __bfloat162float(hi));
        __nv_bfloat16* dst = Wb + (size_t)n * KP;
        dst[k] = hi; dst[512 + k] = lo;
    }
}

__global__ void k_gather(const int* __restrict__ X, const float* __restrict__ emb) {
    int row = blockIdx.x;
    int t = row / BB, b = row % BB;
    int tok = X[b * TT + t];
    const float* src = emb + (size_t)tok * EE;
    for (int e = threadIdx.x; e < EP; e += blockDim.x)
        g_xe[(size_t)row * EP + e] = (e < EE) ? src[e] : 0.0f;
}

// ---------------- embedding GEMM (fp32, K=112, proven) ----------------
__global__ void __launch_bounds__(256) k_gemm(const float* __restrict__ bias) {
    const float* A = g_xe; const float* W = g_W0p; const int K = EP;
    float* C = g_G;

    __shared__ float As[16][132];
    __shared__ float Bs[16][132];

    int m0 = blockIdx.y * 128, n0 = blockIdx.x * 128;
    int tx = threadIdx.x;
    int tn = tx & 15, tm = tx >> 4;

    unsigned long long acc[8][4];
#pragma unroll
    for (int i = 0; i < 8; i++)
#pragma unroll
        for (int j = 0; j < 4; j++) acc[i][j] = 0ull;

    int nt = K / 16;
    float4 va[2], vb[2];
#pragma unroll
    for (int i = 0; i < 2; i++) {
        int id = i * 256 + tx;
        int row = id >> 2, kq = (id & 3) * 4;
        va[i] = *(const float4*)(A + (size_t)(m0 + row) * K + kq);
        vb[i] = *(const float4*)(W + (size_t)(n0 + row) * K + kq);
    }

#pragma unroll 1
    for (int kt = 0; kt < nt; kt++) {
        float4 nva[2], nvb[2];
        if (kt + 1 < nt) {
            int k0n = (kt + 1) * 16;
#pragma unroll
            for (int i = 0; i < 2; i++) {
                int id = i * 256 + tx;
                int row = id >> 2, kq = (id & 3) * 4;
                nva[i] = *(const float4*)(A + (size_t)(m0 + row) * K + k0n + kq);
                nvb[i] = *(const float4*)(W + (size_t)(n0 + row) * K + k0n + kq);
            }
        }
#pragma unroll
        for (int i = 0; i < 2; i++) {
            int id = i * 256 + tx;
            int row = id >> 2, kq = (id & 3) * 4;
            As[kq + 0][row] = va[i].x; As[kq + 1][row] = va[i].y;
            As[kq + 2][row] = va[i].z; As[kq + 3][row] = va[i].w;
            Bs[kq + 0][row] = vb[i].x; Bs[kq + 1][row] = vb[i].y;
            Bs[kq + 2][row] = vb[i].z; Bs[kq + 3][row] = vb[i].w;
        }
        __syncthreads();
#pragma unroll
        for (int k = 0; k < 16; k++) {
            float4 a0 = *(const float4*)&As[k][tm * 4];
            float4 a1 = *(const float4*)&As[k][64 + tm * 4];
            unsigned long long pb[4];
            pb[0] = *(const unsigned long long*)&Bs[k][tn * 4];
            pb[1] = *(const unsigned long long*)&Bs[k][tn * 4 + 2];
            pb[2] = *(const unsigned long long*)&Bs[k][64 + tn * 4];
            pb[3] = *(const unsigned long long*)&Bs[k][64 + tn * 4 + 2];
            float am[8] = { a0.x, a0.y, a0.z, a0.w, a1.x, a1.y, a1.z, a1.w };
#pragma unroll
            for (int mi = 0; mi < 8; mi++) {
                unsigned long long pa = pk2(am[mi], am[mi]);
#pragma unroll
                for (int np = 0; np < 4; np++) fma2(acc[mi][np], pa, pb[np]);
            }
        }
        __syncthreads();
#pragma unroll
        for (int i = 0; i < 2; i++) { va[i] = nva[i]; vb[i] = nvb[i]; }
    }

    float4 bi0 = *(const float4*)(bias + n0 + tn * 4);
    float4 bi1 = *(const float4*)(bias + n0 + 64 + tn * 4);
#pragma unroll
    for (int mi = 0; mi < 8; mi++) {
        int row = m0 + ((mi < 4) ? (tm * 4 + mi) : (64 + tm * 4 + mi - 4));
        float4 o;
        upk2(o.x, o.y, acc[mi][0]); upk2(o.z, o.w, acc[mi][1]);
        o.x += bi0.x; o.y += bi0.y; o.z += bi0.z; o.w += bi0.w;
        *(float4*)(C + (size_t)row * G4 + n0 + tn * 4) = o;
        upk2(o.x, o.y, acc[mi][2]); upk2(o.z, o.w, acc[mi][3]);
        o.x += bi1.x; o.y += bi1.y; o.z += bi1.z; o.w += bi1.w;
        *(float4*)(C + (size_t)row * G4 + n0 + 64 + tn * 4) = o;
    }
}

// ---------------- layer-1 input GEMM: split-bf16 mma.sync ----------------
// C[51200, 2048] = h0 @ W_ih1^T + b1.  3 terms (Ahi*Whi, Ahi*Wlo, Alo*Whi).
// CTA 128m x 64n, 8 warps (4m x 2n of 32x32). cp.async 3-buffer pipeline.
#define GBF_AB 16384
#define GBF_BB 8192
#define GBF_BOFF (3 * GBF_AB)
#define GBF_SMEM (3 * GBF_AB + 3 * GBF_BB)

__global__ void __launch_bounds__(256) k_gemm_bf(const float* __restrict__ bias) {
    extern __shared__ char smem[];
    uint32_t sbase = smem_u32(smem);
    int tx = threadIdx.x;
    int wid = tx >> 5, lane = tx & 31;
    int wm = wid & 3, wn = wid >> 2;
    int n0 = blockIdx.x * 64;
    size_t mr0 = (size_t)blockIdx.y * 128;

    // ldsm addressing
    int Arow = wm * 32 + (lane & 15);
    uint32_t ArowOff = (uint32_t)Arow * 128;
    int Asw = Arow & 7, Alsel = lane >> 4;
    int Brow = wn * 32 + (lane & 7) + ((lane >> 4) << 3);
    int Bksel = (lane >> 3) & 1;
    uint32_t BrowOff0 = (uint32_t)Brow * 128;
    uint32_t BrowOff1 = (uint32_t)(Brow + 16) * 128;
    int Bsw0 = Brow & 7, Bsw1 = (Brow + 16) & 7;

    float d[2][4][4];
#pragma unroll
    for (int a = 0; a < 2; a++)
#pragma unroll
        for (int b = 0; b < 4; b++)
#pragma unroll
            for (int q = 0; q < 4; q++) d[a][b][q] = 0.f;

    // issue chunk it (term = it>>3, ch = it&7)
    auto issue = [&](int it) {
        int term = it >> 3, ch = it & 7;
        const __nv_bfloat16* Apl = g_h0b[term == 2 ? 1 : 0];
        int acol = ch * 64;
        int bc16 = ch * 8 + (term == 1 ? 64 : 0);
        uint32_t Ab = sbase + (uint32_t)(it % 3) * GBF_AB;
        uint32_t Bb = sbase + GBF_BOFF + (uint32_t)(it % 3) * GBF_BB;
#pragma unroll
        for (int i = 0; i < 4; i++) {
            int u = i * 256 + tx, r = u >> 3, c16 = u & 7;
            cp16(Ab + r * 128 + (((uint32_t)(c16 ^ (r & 7))) << 4),
                 Apl + (mr0 + r) * HH + acol + c16 * 8);
        }
#pragma unroll
        for (int i = 0; i < 2; i++) {
            int u = i * 256 + tx, n = u >> 3, c16 = u & 7;
            cp16(Bb + n * 128 + (((uint32_t)(c16 ^ (n & 7))) << 4),
                 g_Wib + (size_t)(n0 + n) * KP + (bc16 + c16) * 8);
        }
    };

    issue(0); CP_COMMIT();
    issue(1); CP_COMMIT();

#pragma unroll 1
    for (int it = 0; it < 24; it++) {
        if (it < 23) { CP_WAIT(1); } else { CP_WAIT(0); }
        __syncthreads();
        if (it + 2 < 24) { issue(it + 2); CP_COMMIT(); }
        uint32_t Ab = sbase + (uint32_t)(it % 3) * GBF_AB;
        uint32_t Bb = sbase + GBF_BOFF + (uint32_t)(it % 3) * GBF_BB;
#pragma unroll
        for (int ks = 0; ks < 4; ks++) {
            uint32_t a0[4], a1[4];
            uint32_t aoff = (uint32_t)(((ks * 2 + Alsel) ^ Asw) << 4);
            ldsm4(a0, Ab + ArowOff + aoff);
            ldsm4(a1, Ab + ArowOff + 2048 + aoff);     // FIX: +16 rows * 128B (was 4096)
            uint32_t b0[4], b1[4];
            ldsm4(b0, Bb + BrowOff0 + (uint32_t)(((ks * 2 + Bksel) ^ Bsw0) << 4));
            ldsm4(b1, Bb + BrowOff1 + (uint32_t)(((ks * 2 + Bksel) ^ Bsw1) << 4));
            mma16816(d[0][0], a0, b0); mma16816(d[0][1], a0, b0 + 2);
            mma16816(d[0][2], a0, b1); mma16816(d[0][3], a0, b1 + 2);
            mma16816(d[1][0], a1, b0); mma16816(d[1][1], a1, b0 + 2);
            mma16816(d[1][2], a1, b1); mma16816(d[1][3], a1, b1 + 2);
        }
        __syncthreads();
    }

    // epilogue: add bias, write g_G
    int r_l = lane >> 2, c_l = (lane & 3) * 2;
#pragma unroll
    for (int mi = 0; mi < 2; mi++)
#pragma unroll
        for (int ni = 0; ni < 4; ni++) {
            size_t row = mr0 + wm * 32 + mi * 16 + r_l;
            int col = n0 + wn * 32 + ni * 8 + c_l;
            float b0v = bias[col], b1v = bias[col + 1];
            *(float2*)(g_G + row * G4 + col) = make_float2(d[mi][ni][0] + b0v, d[mi][ni][1] + b1v);
            *(float2*)(g_G + (row + 8) * G4 + col) = make_float2(d[mi][ni][2] + b0v, d[mi][ni][3] + b1v);
        }
}

// ---------------- mma.sync persistent recurrence ----------------
// 128 CTAs (32 j-tiles x 4 m-groups), 256 threads.
// cp.async 4-buffer depth-3 staging; B loads via ldmatrix.x4 (16n per load).
#define ABUF_SZ  16384
#define WS_OFF   65536
#define GB_OFF   196608
#define GB_STRIDE 68
#define RS_SMEM  214016

template<int LAYER>
__global__ void __launch_bounds__(256) k_recur() {
    extern __shared__ char smem[];
    uint32_t sbase = smem_u32(smem);
    float* Gbuf = (float*)(smem + GB_OFF);
    int tx = threadIdx.x;
    int wid = tx >> 5, lane = tx & 31;
    int wm = wid >> 2, wn = wid & 3;          // warp tile: 32m x 16n
    int j0 = blockIdx.x * 16;
    int m0 = blockIdx.y * 64;
    unsigned* bar = &g_bar[LAYER][blockIdx.y];
    const __nv_bfloat16* Wb = LAYER ? g_Wb1 : g_Wb0;

    // ---- stage W slab once: Ws[n][1024], n = g*16+jj ----
    for (int u = tx; u < 8192; u += 256) {
        int n = u >> 7, c16 = u & 127;
        int wrow = (n >> 4) * HH + j0 + (n & 15);
        uint4 v = *(const uint4*)(Wb + (size_t)wrow * KP + c16 * 8);
        *(uint4*)(smem + WS_OFF + n * 2048 + ((c16 ^ (n & 7)) << 4)) = v;
    }
    __syncthreads();

    // ldsm addressing
    int Arow = wm * 32 + (lane & 15);
    uint32_t AoffRow = (uint32_t)Arow * 256;
    int Asw = Arow & 7, Alsel = lane >> 4;
    int Brow = wn * 16 + (lane & 7) + ((lane >> 4) << 3);
    uint32_t BrowBase = sbase + WS_OFF + (uint32_t)Brow * 2048;
    int Bsw = Brow & 7, Bksel = (lane >> 3) & 1;

    // epilogue ownership
    int mym = tx >> 2, jq = tx & 3;
    size_t hoff = (size_t)(m0 + mym) * HH + j0 + jq * 4;
    float cst4[4] = {0.f, 0.f, 0.f, 0.f};
    float pool4[4] = {-FLT_MAX, -FLT_MAX, -FLT_MAX, -FLT_MAX};
    int lastv = (LAYER == 1) ? g_last[m0 + mym] : 0;
    float4 gvv[4];
    {
        const float* gr = g_G + (size_t)(m0 + mym) * G4 + j0 + jq * 4;
#pragma unroll
        for (int g = 0; g < 4; g++) gvv[g] = __ldcg((const float4*)(gr + g * 512));
    }

    for (int t = 0; t < TT; t++) {
        if (t > 0) {
            int ring = (t - 1) & 3;
            float d[2][2][4];
#pragma unroll
            for (int a = 0; a < 2; a++)
#pragma unroll
                for (int b = 0; b < 2; b++)
#pragma unroll
                    for (int q = 0; q < 4; q++) d[a][b][q] = 0.f;

            auto issue = [&](int c) {
                const __nv_bfloat16* pl = g_hb[ring][c >> 2];
                int ck = (c & 3) * 128;
                uint32_t Ab = sbase + (uint32_t)(c & 3) * ABUF_SZ;
#pragma unroll
                for (int i = 0; i < 4; i++) {
                    int u = i * 256 + tx, r = u >> 4, c16 = u & 15;
                    cp16(Ab + r * 256 + (((uint32_t)(c16 ^ (r & 7))) << 4),
                         pl + (size_t)(m0 + r) * HH + ck + c16 * 8);
                }
            };
            issue(0); CP_COMMIT();
            issue(1); CP_COMMIT();
            issue(2); CP_COMMIT();

#pragma unroll 1
            for (int c = 0; c < 8; c++) {
                if (c < 6) { CP_WAIT(2); }
                else if (c == 6) { CP_WAIT(1); }
                else { CP_WAIT(0); }
                __syncthreads();
                if (c + 3 < 8) { issue(c + 3); CP_COMMIT(); }
                uint32_t AbufBase = sbase + (uint32_t)(c & 3) * ABUF_SZ + AoffRow;
#pragma unroll
                for (int ks = 0; ks < 8; ks++) {
                    uint32_t a0[4], a1[4];
                    uint32_t aoff = (uint32_t)(((ks * 2 + Alsel) ^ Asw) << 4);
                    ldsm4(a0, AbufBase + aoff);
                    ldsm4(a1, AbufBase + 16 * 256 + aoff);
                    int c16h = (c & 3) * 16 + ks * 2;
                    {   // term vs Whi
                        uint32_t bb[4];
                        ldsm4(bb, BrowBase + (uint32_t)((((c16h + Bksel)) ^ Bsw) << 4));
                        mma16816(d[0][0], a0, bb); mma16816(d[0][1], a0, bb + 2);
                        mma16816(d[1][0], a1, bb); mma16816(d[1][1], a1, bb + 2);
                    }
                    if (c < 4) {   // A-hi also vs Wlo
                        uint32_t bb[4];
                        ldsm4(bb, BrowBase + (uint32_t)((((c16h + 64 + Bksel)) ^ Bsw) << 4));
                        mma16816(d[0][0], a0, bb); mma16816(d[0][1], a0, bb + 2);
                        mma16816(d[1][0], a1, bb); mma16816(d[1][1], a1, bb + 2);
                    }
                }
            }
            __syncthreads();
            // store C fragments to gate buffer
            {
                int row = wm * 32 + (lane >> 2);
                int col = wn * 16 + (lane & 3) * 2;
#pragma unroll
                for (int mi = 0; mi < 2; mi++)
#pragma unroll
                    for (int ni = 0; ni < 2; ni++) {
                        int rr = row + mi * 16, cc = col + ni * 8;
                        *(float2*)&Gbuf[rr * GB_STRIDE + cc] = make_float2(d[mi][ni][0], d[mi][ni][1]);
                        *(float2*)&Gbuf[(rr + 8) * GB_STRIDE + cc] = make_float2(d[mi][ni][2], d[mi][ni][3]);
                    }
            }
            __syncthreads();
        }

        // ---- epilogue ----
        {
            float gg[4][4];
#pragma unroll
            for (int g = 0; g < 4; g++) {
                if (t > 0) {
                    float4 q = *(const float4*)&Gbuf[mym * GB_STRIDE + g * 16 + jq * 4];
                    gg[g][0] = q.x + ((const float*)&gvv[g])[0];
                    gg[g][1] = q.y + ((const float*)&gvv[g])[1];
                    gg[g][2] = q.z + ((const float*)&gvv[g])[2];
                    gg[g][3] = q.w + ((const float*)&gvv[g])[3];
                } else {
                    gg[g][0] = ((const float*)&gvv[g])[0];
                    gg[g][1] = ((const float*)&gvv[g])[1];
                    gg[g][2] = ((const float*)&gvv[g])[2];
                    gg[g][3] = ((const float*)&gvv[g])[3];
                }
            }
            float h4[4];
#pragma unroll
            for (int j = 0; j < 4; j++) {
                float cc = sigf(gg[1][j]) * cst4[j] + sigf(gg[0][j]) * tanhf_(gg[2][j]);
                cst4[j] = cc;
                h4[j] = sigf(gg[3][j]) * tanhf_(cc);
                if (LAYER == 1 && t <= lastv) pool4[j] = fmaxf(pool4[j], h4[j]);
            }
            unsigned hw[2], lw[2];
#pragma unroll
            for (int q = 0; q < 2; q++) {
                float h0 = h4[2 * q], h1 = h4[2 * q + 1];
                __nv_bfloat16 b0 = __float2bfloat16(h0), b1 = __float2bfloat16(h1);
                float r0 = h0 - __bfloat162float(b0), r1 = h1 - __bfloat162float(b1);
                hw[q] = pack_bf16(__bfloat162float(b0), __bfloat162float(b1));
                lw[q] = pack_bf16(r0, r1);
            }
            int wring = t & 3;
            __stcg((uint2*)&g_hb[wring][0][hoff], make_uint2(hw[0], hw[1]));
            __stcg((uint2*)&g_hb[wring][1][hoff], make_uint2(lw[0], lw[1]));
            if (LAYER == 0) {
                size_t aoff = (size_t)t * BB * HH + hoff;
                __stcg((uint2*)&g_h0b[0][aoff], make_uint2(hw[0], hw[1]));
                __stcg((uint2*)&g_h0b[1][aoff], make_uint2(lw[0], lw[1]));
            }
        }

        // ---- inter-step barrier ----
        if (t != TT - 1) {
            __threadfence();
            __syncthreads();
            if (tx == 0) bar_arrive_release(bar);
            {
                const float* gr = g_G + (size_t)(t + 1) * BB * G4
                                + (size_t)(m0 + mym) * G4 + j0 + jq * 4;
#pragma unroll
                for (int g = 0; g < 4; g++) gvv[g] = __ldcg((const float4*)(gr + g * 512));
            }
            if (tx == 0) {
                unsigned target = 32u * (unsigned)(t + 1);
                while (bar_ld_acquire(bar) < target) { }
            }
            __syncthreads();
            __threadfence();
        }
    }

    if (LAYER == 1) {
        *(float4*)&g_pooled[hoff] = make_float4(pool4[0], pool4[1], pool4[2], pool4[3]);
    }
}

// ---------------- final projection ----------------
__global__ void k_logits(const float* __restrict__ Wout, const float* __restrict__ bout,
                         float* __restrict__ out) {
    int b = blockIdx.x;
    int tx = threadIdx.x;
    float p[NCLS] = {0, 0, 0, 0, 0};
    for (int k = tx; k < HH; k += 128) {
        float v = g_pooled[b * HH + k];
#pragma unroll
        for (int c = 0; c < NCLS; c++) p[c] += v * Wout[c * HH + k];
    }
#pragma unroll
    for (int off = 16; off; off >>= 1)
#pragma unroll
        for (int c = 0; c < NCLS; c++) p[c] += __shfl_down_sync(0xffffffffu, p[c], off);
    __shared__ float red[4][NCLS];
    if ((tx & 31) == 0)
#pragma unroll
        for (int c = 0; c < NCLS; c++) red[tx >> 5][c] = p[c];
    __syncthreads();
    if (tx == 0) {
#pragma unroll
        for (int c = 0; c < NCLS; c++)
            out[b * NCLS + c] = red[0][c] + red[1][c] + red[2][c] + red[3][c] + bout[c];
    }
}

// ---------------- launch ----------------
extern "C" void kernel_launch(void* const* d_in, const int* in_sizes, int n_in,
                              void* d_out, int out_size) {
    (void)in_sizes; (void)n_in; (void)out_size;
    const int*   X      = (const int*)d_in[0];
    const float* emb    = (const float*)d_in[1];
    const float* W_ih0  = (const float*)d_in[2];
    const float* W_hh0  = (const float*)d_in[3];
    const float* b0     = (const float*)d_in[4];
    const float* W_ih1  = (const float*)d_in[5];
    const float* W_hh1  = (const float*)d_in[6];
    const float* b1     = (const float*)d_in[7];
    const float* W_out  = (const float*)d_in[8];
    const float* b_out  = (const float*)d_in[9];
    float* out = (float*)d_out;

    cudaFuncSetAttribute(k_recur<0>, cudaFuncAttributeMaxDynamicSharedMemorySize, RS_SMEM);
    cudaFuncSetAttribute(k_recur<1>, cudaFuncAttributeMaxDynamicSharedMemorySize, RS_SMEM);
    cudaFuncSetAttribute(k_gemm_bf, cudaFuncAttributeMaxDynamicSharedMemorySize, GBF_SMEM);

    int prep_items = 8 + P0 + 3 * CW;
    // order keeps k_recur<0> in the ncu capture slot (launch 4)
    k_prep<<<(prep_items + 255) / 256, 256>>>(W_ih0, W_hh0, W_hh1, W_ih1);  // 1
    k_gather<<<MROWS, 128>>>(X, emb);                                        // 2
    k_gemm<<<dim3(16, 400), 256>>>(b0);                                      // 3
    k_recur<0><<<dim3(32, 4), 256, RS_SMEM>>>();                             // 4  <- capture target
    k_last<<<1, 256>>>(X);                                                   // 5
    k_gemm_bf<<<dim3(32, 400), 256, GBF_SMEM>>>(b1);                         // 6
    k_recur<1><<<dim3(32, 4), 256, RS_SMEM>>>();                             // 7
    k_logits<<<BB, 128>>>(W_out, b_out, out);                                // 8
}